// round 5
// baseline (speedup 1.0000x reference)
#include <cuda_runtime.h>
#include <math.h>
#include <stdint.h>

// BitNet MoE layer, GB300. Pipeline (all graph-capturable launches, no allocs):
//   k_zero -> weight quant (reduce/finalize/sign) -> router(+logits out)
//   -> top2 compaction lists -> per expert: xquant, dual int8 GEMM (gate/up,
//   silu*up epilogue), hidden rmsnorm+quant, int8 down GEMM w/ scatter-add
//   -> final clip.
// Integer GEMMs via __dp4a are mathematically exact vs the fp reference
// (quantized values are small integers times per-row scales).

#define TOK  8192
#define HD   768
#define ID   2048
#define NEXP 9          // 8 routed + 1 shared (slot 8)
#define NMAT 27         // 9 x {Wg, Wu, Wd}
#define NW   (ID*HD)    // elements per weight matrix (same for all 27)

// ---------------- scratch (device globals; allocation-free) ----------------
__device__ __align__(16) int8_t g_qw[3][NEXP][NW];   // quantized weights {-1,0,1}
__device__ double g_part[NMAT * 256 * 2];
__device__ double g_mean[NMAT];
__device__ float  g_wscale[NMAT];
__device__ float  g_logits_scratch[TOK * 8];
__device__ int    g_te1[TOK], g_te2[TOK];
__device__ float  g_tw1[TOK], g_tw2[TOK];
__device__ int    g_cnt[NEXP];
__device__ int    g_lidx[NEXP * TOK];
__device__ float  g_lw[NEXP * TOK];
__device__ __align__(16) int8_t g_xg[TOK * HD];
__device__ __align__(16) int8_t g_xu[TOK * HD];
__device__ float  g_ag[TOK], g_au[TOK];
__device__ float  g_hidden[(size_t)TOK * ID];
__device__ __align__(16) int8_t g_hq[(size_t)TOK * ID];
__device__ float  g_ah[TOK];

__device__ __forceinline__ float clipf(float v, float lo, float hi) {
    return fminf(fmaxf(v, lo), hi);
}

// ---------------- init ----------------
__global__ void k_zero(float* out, int n) {
    int i = blockIdx.x * blockDim.x + threadIdx.x;
    if (i < n) out[i] = 0.f;
    if (i < NEXP) g_cnt[i] = 0;
}

// ---------------- weight quantization ----------------
__global__ void k_wred(const float* __restrict__ w, int n, int m) {
    __shared__ double ss[256], sa[256];
    int tid = threadIdx.x;
    double s = 0.0, a = 0.0;
    for (int i = blockIdx.x * 256 + tid; i < n; i += 256 * 256) {
        float v = w[i];
        s += (double)v;
        a += (double)fabsf(v);
    }
    ss[tid] = s; sa[tid] = a;
    __syncthreads();
    for (int o = 128; o; o >>= 1) {
        if (tid < o) { ss[tid] += ss[tid + o]; sa[tid] += sa[tid + o]; }
        __syncthreads();
    }
    if (tid == 0) {
        g_part[(m * 256 + blockIdx.x) * 2 + 0] = ss[0];
        g_part[(m * 256 + blockIdx.x) * 2 + 1] = sa[0];
    }
}

__global__ void k_wfin(int n) {
    int m = blockIdx.x;
    int tid = threadIdx.x;
    __shared__ double ss[256], sa[256];
    ss[tid] = g_part[(m * 256 + tid) * 2 + 0];
    sa[tid] = g_part[(m * 256 + tid) * 2 + 1];
    __syncthreads();
    for (int o = 128; o; o >>= 1) {
        if (tid < o) { ss[tid] += ss[tid + o]; sa[tid] += sa[tid + o]; }
        __syncthreads();
    }
    if (tid == 0) {
        g_mean[m] = ss[0] / (double)n;
        double sc = sa[0] / (double)n;
        if (sc < 1e-8) sc = 1e-8;
        g_wscale[m] = (float)sc;
    }
}

__global__ void k_wq(const float* __restrict__ w, int n, int kind, int slot, int m) {
    int i = blockIdx.x * blockDim.x + threadIdx.x;
    if (i >= n) return;
    double d = (double)w[i] - g_mean[m];
    g_qw[kind][slot][i] = (d > 0.0) ? (int8_t)1 : ((d < 0.0) ? (int8_t)-1 : (int8_t)0);
}

// ---------------- router: logits, softmax, top-2 ----------------
__global__ __launch_bounds__(128) void k_router(const float* __restrict__ x,
                                                const float* __restrict__ rw,
                                                const float* __restrict__ rb,
                                                float* __restrict__ logits_out) {
    int t = blockIdx.x, tid = threadIdx.x;
    const float* xr = x + (size_t)t * HD;
    float acc[8];
#pragma unroll
    for (int e = 0; e < 8; e++) acc[e] = 0.f;
    for (int h = tid; h < HD; h += 128) {
        float xv = xr[h];
#pragma unroll
        for (int e = 0; e < 8; e++) acc[e] += xv * rw[e * HD + h];
    }
    __shared__ float s[8][128];
#pragma unroll
    for (int e = 0; e < 8; e++) s[e][tid] = acc[e];
    __syncthreads();
    for (int o = 64; o; o >>= 1) {
        if (tid < o) {
#pragma unroll
            for (int e = 0; e < 8; e++) s[e][tid] += s[e][tid + o];
        }
        __syncthreads();
    }
    if (tid == 0) {
        float l[8], p[8];
        float mx = -1e30f;
#pragma unroll
        for (int e = 0; e < 8; e++) {
            l[e] = s[e][0] + rb[e];
            logits_out[t * 8 + e] = l[e];
            mx = fmaxf(mx, l[e]);
        }
        float ps = 0.f;
#pragma unroll
        for (int e = 0; e < 8; e++) { p[e] = expf(l[e] - mx); ps += p[e]; }
#pragma unroll
        for (int e = 0; e < 8; e++) p[e] /= ps;
        int i1 = 0;
#pragma unroll
        for (int e = 1; e < 8; e++) if (p[e] > p[i1]) i1 = e;
        int i2 = -1;
#pragma unroll
        for (int e = 0; e < 8; e++) {
            if (e == i1) continue;
            if (i2 < 0 || p[e] > p[i2]) i2 = e;
        }
        float den = p[i1] + p[i2] + 1e-8f;
        g_te1[t] = i1; g_te2[t] = i2;
        g_tw1[t] = p[i1] / den; g_tw2[t] = p[i2] / den;
    }
}

__global__ void k_lists() {
    int t = blockIdx.x * blockDim.x + threadIdx.x;
    if (t >= TOK) return;
    int e1 = g_te1[t];
    int p1 = atomicAdd(&g_cnt[e1], 1);
    g_lidx[e1 * TOK + p1] = t;
    g_lw[e1 * TOK + p1] = g_tw1[t];
    int e2 = g_te2[t];
    int p2 = atomicAdd(&g_cnt[e2], 1);
    g_lidx[e2 * TOK + p2] = t;
    g_lw[e2 * TOK + p2] = g_tw2[t];
    // shared expert: identity list, weight 1
    g_lidx[8 * TOK + t] = t;
    g_lw[8 * TOK + t] = 1.f;
    if (t == 0) g_cnt[8] = TOK;
}

// ---------------- activation rmsnorm + quant (input x, per expert) ----------------
__global__ __launch_bounds__(256) void k_xq(int e, const float* __restrict__ x,
                                            const float* __restrict__ nwg,
                                            const float* __restrict__ nwu) {
    int r = blockIdx.x;
    if (r >= g_cnt[e]) return;
    int t = g_lidx[e * TOK + r];
    __shared__ float sx[HD];
    __shared__ float red[256];
    __shared__ float bc[3];
    int tid = threadIdx.x;
    float ss = 0.f;
    const float* xr = x + (size_t)t * HD;
    for (int j = tid; j < HD; j += 256) {
        float v = clipf(xr[j], -100.f, 100.f);
        sx[j] = v;
        ss += v * v;
    }
    red[tid] = ss; __syncthreads();
    for (int o = 128; o; o >>= 1) { if (tid < o) red[tid] += red[tid + o]; __syncthreads(); }
    if (tid == 0) {
        float var = fmaxf(red[0] / (float)HD, 1e-5f);
        bc[0] = 1.f / sqrtf(var + 1e-5f);
    }
    __syncthreads();
    float rinv = bc[0];
    float mg = 0.f, mu = 0.f;
    for (int j = tid; j < HD; j += 256) {
        float xh = clipf(sx[j] * rinv, -10.f, 10.f);
        sx[j] = xh;
        float vg = clipf(nwg[j] * xh, -50.f, 50.f);
        float vu = clipf(nwu[j] * xh, -50.f, 50.f);
        mg = fmaxf(mg, fabsf(vg));
        mu = fmaxf(mu, fabsf(vu));
    }
    __syncthreads();
    red[tid] = mg; __syncthreads();
    for (int o = 128; o; o >>= 1) { if (tid < o) red[tid] = fmaxf(red[tid], red[tid + o]); __syncthreads(); }
    if (tid == 0) bc[1] = fmaxf(red[0], 1e-4f);
    __syncthreads();
    red[tid] = mu; __syncthreads();
    for (int o = 128; o; o >>= 1) { if (tid < o) red[tid] = fmaxf(red[tid], red[tid + o]); __syncthreads(); }
    if (tid == 0) bc[2] = fmaxf(red[0], 1e-4f);
    __syncthreads();
    float maxg = bc[1], maxu = bc[2];
    float scg = 127.f / maxg, scu = 127.f / maxu;
    if (tid == 0) { g_ag[r] = maxg / 127.f; g_au[r] = maxu / 127.f; }
    for (int j = tid; j < HD; j += 256) {
        float xh = sx[j];
        float vg = clipf(nwg[j] * xh, -50.f, 50.f);
        float vu = clipf(nwu[j] * xh, -50.f, 50.f);
        int qg = (int)rintf(vg * scg); qg = max(-128, min(127, qg));
        int qu = (int)rintf(vu * scu); qu = max(-128, min(127, qu));
        g_xg[(size_t)r * HD + j] = (int8_t)qg;
        g_xu[(size_t)r * HD + j] = (int8_t)qu;
    }
}

// ---------------- hidden rmsnorm + quant ----------------
__global__ __launch_bounds__(256) void k_hq(int e, const float* __restrict__ nw) {
    int r = blockIdx.x;
    if (r >= g_cnt[e]) return;
    __shared__ float sx[ID];
    __shared__ float red[256];
    __shared__ float bc[2];
    int tid = threadIdx.x;
    float ss = 0.f;
    const float* hr = g_hidden + (size_t)r * ID;
    for (int j = tid; j < ID; j += 256) {
        float v = clipf(hr[j], -100.f, 100.f);
        sx[j] = v;
        ss += v * v;
    }
    red[tid] = ss; __syncthreads();
    for (int o = 128; o; o >>= 1) { if (tid < o) red[tid] += red[tid + o]; __syncthreads(); }
    if (tid == 0) {
        float var = fmaxf(red[0] / (float)ID, 1e-5f);
        bc[0] = 1.f / sqrtf(var + 1e-5f);
    }
    __syncthreads();
    float rinv = bc[0];
    float m = 0.f;
    for (int j = tid; j < ID; j += 256) {
        float xh = clipf(sx[j] * rinv, -10.f, 10.f);
        sx[j] = xh;
        float v = clipf(nw[j] * xh, -50.f, 50.f);
        m = fmaxf(m, fabsf(v));
    }
    __syncthreads();
    red[tid] = m; __syncthreads();
    for (int o = 128; o; o >>= 1) { if (tid < o) red[tid] = fmaxf(red[tid], red[tid + o]); __syncthreads(); }
    if (tid == 0) bc[1] = fmaxf(red[0], 1e-4f);
    __syncthreads();
    float maxv = bc[1];
    float sc = 127.f / maxv;
    if (tid == 0) g_ah[r] = maxv / 127.f;
    for (int j = tid; j < ID; j += 256) {
        float v = clipf(nw[j] * sx[j], -50.f, 50.f);
        int q = (int)rintf(v * sc); q = max(-128, min(127, q));
        g_hq[(size_t)r * ID + j] = (int8_t)q;
    }
}

// ---------------- dp4a helper ----------------
__device__ __forceinline__ int dp4(int4 a, int4 b, int c) {
    c = __dp4a(a.x, b.x, c);
    c = __dp4a(a.y, b.y, c);
    c = __dp4a(a.z, b.z, c);
    c = __dp4a(a.w, b.w, c);
    return c;
}

// ---------------- GEMM 1: dual gate/up int8, silu(gate)*up epilogue ----------------
// A: g_xg/g_xu [n, 768] int8 compact; B: g_qw[0/1][e] [2048, 768]; C: g_hidden [n, 2048]
__global__ __launch_bounds__(256) void k_gemm_gu(int e) {
    int n = g_cnt[e];
    int m0 = blockIdx.x * 64;
    if (m0 >= n) return;
    int n0 = blockIdx.y * 64;

    __shared__ int4 sAg[64][4], sAu[64][4];
    __shared__ int4 sBg[4][4][17], sBu[4][4][17];  // [kk][j][tx] (padded)

    const int4* Ag = (const int4*)g_xg;
    const int4* Au = (const int4*)g_xu;
    const int4* Bg = (const int4*)&g_qw[0][e][0];
    const int4* Bu = (const int4*)&g_qw[1][e][0];
    const int KI4 = HD / 16;  // 48 int4 per row

    int tid = threadIdx.x;
    int lr = tid >> 2, lc = tid & 3;
    int tx = tid & 15, ty = tid >> 4;
    int lbx = lr >> 2, lbj = lr & 3;

    int accg[4][4] = {}, accu[4][4] = {};
    const int4 z = make_int4(0, 0, 0, 0);

    for (int kb = 0; kb < HD / 64; kb++) {
        __syncthreads();
        int ra = m0 + lr;
        sAg[lr][lc] = (ra < n) ? Ag[(size_t)ra * KI4 + kb * 4 + lc] : z;
        sAu[lr][lc] = (ra < n) ? Au[(size_t)ra * KI4 + kb * 4 + lc] : z;
        int rb_ = n0 + lr;
        sBg[lc][lbj][lbx] = Bg[(size_t)rb_ * KI4 + kb * 4 + lc];
        sBu[lc][lbj][lbx] = Bu[(size_t)rb_ * KI4 + kb * 4 + lc];
        __syncthreads();
#pragma unroll
        for (int kk = 0; kk < 4; kk++) {
            int4 bg[4], bu[4];
#pragma unroll
            for (int j = 0; j < 4; j++) { bg[j] = sBg[kk][j][tx]; bu[j] = sBu[kk][j][tx]; }
#pragma unroll
            for (int i = 0; i < 4; i++) {
                int4 ag = sAg[ty * 4 + i][kk];
                int4 au = sAu[ty * 4 + i][kk];
#pragma unroll
                for (int j = 0; j < 4; j++) {
                    accg[i][j] = dp4(ag, bg[j], accg[i][j]);
                    accu[i][j] = dp4(au, bu[j], accu[i][j]);
                }
            }
        }
    }

    float wsg = g_wscale[0 * NEXP + e];
    float wsu = g_wscale[1 * NEXP + e];
#pragma unroll
    for (int i = 0; i < 4; i++) {
        int r = m0 + ty * 4 + i;
        if (r < n) {
            float sg = g_ag[r] * wsg;
            float su = g_au[r] * wsu;
#pragma unroll
            for (int j = 0; j < 4; j++) {
                int c = n0 + tx * 4 + j;
                float gg = clipf((float)accg[i][j] * sg, -20.f, 20.f);
                float uu = (float)accu[i][j] * su;
                float h = (gg / (1.f + expf(-gg))) * uu;
                g_hidden[(size_t)r * ID + c] = clipf(h, -1000.f, 1000.f);
            }
        }
    }
}

// ---------------- GEMM 2: down int8, scatter-accumulate into out ----------------
// A: g_hq [n, 2048]; B: g_qw[2][e] [768, 2048]; out[t*768 + c] += lw * y
__global__ __launch_bounds__(256) void k_gemm_d(int e, float* __restrict__ out) {
    int n = g_cnt[e];
    int m0 = blockIdx.x * 64;
    if (m0 >= n) return;
    int n0 = blockIdx.y * 64;

    __shared__ int4 sA[64][4];
    __shared__ int4 sB[4][4][17];

    const int4* A = (const int4*)g_hq;
    const int4* B = (const int4*)&g_qw[2][e][0];
    const int KI4 = ID / 16;  // 128

    int tid = threadIdx.x;
    int lr = tid >> 2, lc = tid & 3;
    int tx = tid & 15, ty = tid >> 4;
    int lbx = lr >> 2, lbj = lr & 3;

    int acc[4][4] = {};
    const int4 z = make_int4(0, 0, 0, 0);

    for (int kb = 0; kb < ID / 64; kb++) {
        __syncthreads();
        int ra = m0 + lr;
        sA[lr][lc] = (ra < n) ? A[(size_t)ra * KI4 + kb * 4 + lc] : z;
        int rb_ = n0 + lr;
        sB[lc][lbj][lbx] = B[(size_t)rb_ * KI4 + kb * 4 + lc];
        __syncthreads();
#pragma unroll
        for (int kk = 0; kk < 4; kk++) {
            int4 b[4];
#pragma unroll
            for (int j = 0; j < 4; j++) b[j] = sB[kk][j][tx];
#pragma unroll
            for (int i = 0; i < 4; i++) {
                int4 a = sA[ty * 4 + i][kk];
#pragma unroll
                for (int j = 0; j < 4; j++) acc[i][j] = dp4(a, b[j], acc[i][j]);
            }
        }
    }

    float wsd = g_wscale[2 * NEXP + e];
#pragma unroll
    for (int i = 0; i < 4; i++) {
        int r = m0 + ty * 4 + i;
        if (r < n) {
            float s = g_ah[r] * wsd;
            int t = g_lidx[e * TOK + r];
            float lw = g_lw[e * TOK + r];
#pragma unroll
            for (int j = 0; j < 4; j++) {
                int c = n0 + tx * 4 + j;
                out[(size_t)t * HD + c] += lw * ((float)acc[i][j] * s);
            }
        }
    }
}

__global__ void k_clip(float* out, int n) {
    int i = blockIdx.x * blockDim.x + threadIdx.x;
    if (i < n) out[i] = clipf(out[i], -10000.f, 10000.f);
}

// ---------------- launcher ----------------
extern "C" void kernel_launch(void* const* d_in, const int* in_sizes, int n_in,
                              void* d_out, int out_size) {
    const float* x   = (const float*)d_in[0];   // [4,2048,768]
    const float* rw  = (const float*)d_in[1];   // [8,768]
    const float* rb  = (const float*)d_in[2];   // [8]
    const float* Wg  = (const float*)d_in[3];   // [8,2048,768]
    const float* Wu  = (const float*)d_in[4];
    const float* Wd  = (const float*)d_in[5];   // [8,768,2048]
    const float* ng  = (const float*)d_in[6];   // [8,768]
    const float* nu  = (const float*)d_in[7];
    const float* nd  = (const float*)d_in[8];   // [8,2048]
    const float* sWg = (const float*)d_in[9];   // [2048,768]
    const float* sWu = (const float*)d_in[10];
    const float* sWd = (const float*)d_in[11];  // [768,2048]
    const float* sng = (const float*)d_in[12];  // [768]
    const float* snu = (const float*)d_in[13];
    const float* snd = (const float*)d_in[14];  // [2048]
    float* out = (float*)d_out;

    float* logits_dst;
    if (out_size >= TOK * HD + TOK * 8) {
        logits_dst = out + (size_t)TOK * HD;   // (out, router_logits) concatenated
    } else {
        void* p = nullptr;
        cudaGetSymbolAddress(&p, g_logits_scratch);
        logits_dst = (float*)p;
    }

    // zero output accumulator + expert counters
    k_zero<<<(TOK * HD + 255) / 256, 256>>>(out, TOK * HD);

    // weight quantization: reductions, finalize, sign
    for (int e = 0; e < NEXP; e++) {
        const float* pg = (e < 8) ? Wg + (size_t)e * NW : sWg;
        const float* pu = (e < 8) ? Wu + (size_t)e * NW : sWu;
        const float* pd = (e < 8) ? Wd + (size_t)e * NW : sWd;
        k_wred<<<256, 256>>>(pg, NW, 0 * NEXP + e);
        k_wred<<<256, 256>>>(pu, NW, 1 * NEXP + e);
        k_wred<<<256, 256>>>(pd, NW, 2 * NEXP + e);
    }
    k_wfin<<<NMAT, 256>>>(NW);
    for (int e = 0; e < NEXP; e++) {
        const float* pg = (e < 8) ? Wg + (size_t)e * NW : sWg;
        const float* pu = (e < 8) ? Wu + (size_t)e * NW : sWu;
        const float* pd = (e < 8) ? Wd + (size_t)e * NW : sWd;
        k_wq<<<(NW + 255) / 256, 256>>>(pg, NW, 0, e, 0 * NEXP + e);
        k_wq<<<(NW + 255) / 256, 256>>>(pu, NW, 1, e, 1 * NEXP + e);
        k_wq<<<(NW + 255) / 256, 256>>>(pd, NW, 2, e, 2 * NEXP + e);
    }

    // router + top-2 compaction
    k_router<<<TOK, 128>>>(x, rw, rb, logits_dst);
    k_lists<<<TOK / 256, 256>>>();

    // expert passes (sequential; scratch reused; scatter-add into out)
    dim3 g1(TOK / 64, ID / 64);
    dim3 g2(TOK / 64, HD / 64);
    for (int e = 0; e < NEXP; e++) {
        const float* png = (e < 8) ? ng + (size_t)e * HD : sng;
        const float* pnu = (e < 8) ? nu + (size_t)e * HD : snu;
        const float* pnd = (e < 8) ? nd + (size_t)e * ID : snd;
        k_xq<<<TOK, 256>>>(e, x, png, pnu);
        k_gemm_gu<<<g1, 256>>>(e);
        k_hq<<<TOK, 256>>>(e, pnd);
        k_gemm_d<<<g2, 256>>>(e, out);
    }

    k_clip<<<(TOK * HD + 255) / 256, 256>>>(out, TOK * HD);
}

// round 7
// speedup vs baseline: 1.2853x; 1.2853x over previous
#include <cuda_runtime.h>
#include <math.h>
#include <stdint.h>

// BitNet MoE layer, GB300.  R7 = R6 structure (batched weight-quant, all 9
// experts batched into 4 wide kernels, atomicAdd scatter) with the R6 bug
// fixed: hidden activations stored in fp32 (fp16 rounding flipped int8
// re-quantization decisions and pushed rel_err to 3.2e-3).

#define TOK  8192
#define HD   768
#define ID   2048
#define NEXP 9          // 8 routed + 1 shared (slot 8)
#define NMAT 27         // kind*NEXP + e ; kind: 0=Wg 1=Wu 2=Wd
#define NW   (ID*HD)

#define RED_BLK 64      // blocks per matrix in k_wred_all

// ---------------- scratch (device globals; allocation-free) ----------------
__device__ __align__(16) int8_t g_qw[3][NEXP][NW];            // {-1,0,1}
__device__ double g_part[NMAT * RED_BLK * 2];
__device__ double g_mean[NMAT];
__device__ float  g_wscale[NMAT];
__device__ float  g_logits_scratch[TOK * 8];
__device__ int    g_te1[TOK], g_te2[TOK];
__device__ float  g_tw1[TOK], g_tw2[TOK];
__device__ int    g_cnt[NEXP];
__device__ int    g_lidx[NEXP * TOK];
__device__ float  g_lw[NEXP * TOK];
__device__ __align__(16) int8_t g_xg[(size_t)NEXP * TOK * HD];     // 56.6MB
__device__ __align__(16) int8_t g_xu[(size_t)NEXP * TOK * HD];
__device__ float  g_ag[NEXP * TOK], g_au[NEXP * TOK], g_ah[NEXP * TOK];
__device__ __align__(16) float  g_hidden[(size_t)NEXP * TOK * ID]; // 604MB fp32
__device__ __align__(16) int8_t g_hq[(size_t)NEXP * TOK * ID];     // 151MB

__device__ __forceinline__ float clipf(float v, float lo, float hi) {
    return fminf(fmaxf(v, lo), hi);
}

// ---------------- init ----------------
__global__ void k_zero(float* out, int n) {
    int i = blockIdx.x * blockDim.x + threadIdx.x;
    if (i < n) out[i] = 0.f;
    if (i < NEXP) g_cnt[i] = 0;
}

// ---------------- weight quantization (batched) ----------------
__global__ __launch_bounds__(256) void k_wred_all(
    const float* __restrict__ Wg, const float* __restrict__ Wu,
    const float* __restrict__ Wd, const float* __restrict__ sWg,
    const float* __restrict__ sWu, const float* __restrict__ sWd) {
    int m = blockIdx.y;
    int kind = m / NEXP, e = m % NEXP;
    const float* base =
        (kind == 0) ? ((e < 8) ? Wg + (size_t)e * NW : sWg)
      : (kind == 1) ? ((e < 8) ? Wu + (size_t)e * NW : sWu)
                    : ((e < 8) ? Wd + (size_t)e * NW : sWd);
    const float4* w4 = (const float4*)base;
    const int N4 = NW / 4;
    int tid = threadIdx.x;
    float s = 0.f, a = 0.f;
    for (int i = blockIdx.x * 256 + tid; i < N4; i += RED_BLK * 256) {
        float4 v = w4[i];
        s += (v.x + v.y) + (v.z + v.w);
        a += (fabsf(v.x) + fabsf(v.y)) + (fabsf(v.z) + fabsf(v.w));
    }
    __shared__ double ss[256], sa[256];
    ss[tid] = (double)s; sa[tid] = (double)a;
    __syncthreads();
    for (int o = 128; o; o >>= 1) {
        if (tid < o) { ss[tid] += ss[tid + o]; sa[tid] += sa[tid + o]; }
        __syncthreads();
    }
    if (tid == 0) {
        g_part[(m * RED_BLK + blockIdx.x) * 2 + 0] = ss[0];
        g_part[(m * RED_BLK + blockIdx.x) * 2 + 1] = sa[0];
    }
}

__global__ void k_wfin() {
    int m = blockIdx.x, tid = threadIdx.x;   // RED_BLK threads
    __shared__ double ss[RED_BLK], sa[RED_BLK];
    ss[tid] = g_part[(m * RED_BLK + tid) * 2 + 0];
    sa[tid] = g_part[(m * RED_BLK + tid) * 2 + 1];
    __syncthreads();
    for (int o = RED_BLK / 2; o; o >>= 1) {
        if (tid < o) { ss[tid] += ss[tid + o]; sa[tid] += sa[tid + o]; }
        __syncthreads();
    }
    if (tid == 0) {
        g_mean[m] = ss[0] / (double)NW;
        double sc = sa[0] / (double)NW;
        if (sc < 1e-8) sc = 1e-8;
        g_wscale[m] = (float)sc;
    }
}

__global__ __launch_bounds__(256) void k_wq_all(
    const float* __restrict__ Wg, const float* __restrict__ Wu,
    const float* __restrict__ Wd, const float* __restrict__ sWg,
    const float* __restrict__ sWu, const float* __restrict__ sWd) {
    int m = blockIdx.y;
    int kind = m / NEXP, e = m % NEXP;
    const float* base =
        (kind == 0) ? ((e < 8) ? Wg + (size_t)e * NW : sWg)
      : (kind == 1) ? ((e < 8) ? Wu + (size_t)e * NW : sWu)
                    : ((e < 8) ? Wd + (size_t)e * NW : sWd);
    int i = blockIdx.x * 256 + threadIdx.x;
    const int N4 = NW / 4;
    if (i >= N4) return;
    double mean = g_mean[m];
    float4 v = ((const float4*)base)[i];
    char4 q;
    double d;
    d = (double)v.x - mean; q.x = (d > 0.0) ? 1 : ((d < 0.0) ? -1 : 0);
    d = (double)v.y - mean; q.y = (d > 0.0) ? 1 : ((d < 0.0) ? -1 : 0);
    d = (double)v.z - mean; q.z = (d > 0.0) ? 1 : ((d < 0.0) ? -1 : 0);
    d = (double)v.w - mean; q.w = (d > 0.0) ? 1 : ((d < 0.0) ? -1 : 0);
    ((char4*)&g_qw[kind][e][0])[i] = q;
}

// ---------------- router: logits, softmax, top-2 ----------------
__global__ __launch_bounds__(128) void k_router(const float* __restrict__ x,
                                                const float* __restrict__ rw,
                                                const float* __restrict__ rb,
                                                float* __restrict__ logits_out) {
    int t = blockIdx.x, tid = threadIdx.x;
    const float* xr = x + (size_t)t * HD;
    float acc[8];
#pragma unroll
    for (int e = 0; e < 8; e++) acc[e] = 0.f;
    for (int h = tid; h < HD; h += 128) {
        float xv = xr[h];
#pragma unroll
        for (int e = 0; e < 8; e++) acc[e] += xv * rw[e * HD + h];
    }
    __shared__ float s[8][128];
#pragma unroll
    for (int e = 0; e < 8; e++) s[e][tid] = acc[e];
    __syncthreads();
    for (int o = 64; o; o >>= 1) {
        if (tid < o) {
#pragma unroll
            for (int e = 0; e < 8; e++) s[e][tid] += s[e][tid + o];
        }
        __syncthreads();
    }
    if (tid == 0) {
        float l[8], p[8];
        float mx = -1e30f;
#pragma unroll
        for (int e = 0; e < 8; e++) {
            l[e] = s[e][0] + rb[e];
            logits_out[t * 8 + e] = l[e];
            mx = fmaxf(mx, l[e]);
        }
        float ps = 0.f;
#pragma unroll
        for (int e = 0; e < 8; e++) { p[e] = expf(l[e] - mx); ps += p[e]; }
#pragma unroll
        for (int e = 0; e < 8; e++) p[e] /= ps;
        int i1 = 0;
#pragma unroll
        for (int e = 1; e < 8; e++) if (p[e] > p[i1]) i1 = e;
        int i2 = -1;
#pragma unroll
        for (int e = 0; e < 8; e++) {
            if (e == i1) continue;
            if (i2 < 0 || p[e] > p[i2]) i2 = e;
        }
        float den = p[i1] + p[i2] + 1e-8f;
        g_te1[t] = i1; g_te2[t] = i2;
        g_tw1[t] = p[i1] / den; g_tw2[t] = p[i2] / den;
    }
}

__global__ void k_lists() {
    int t = blockIdx.x * blockDim.x + threadIdx.x;
    if (t >= TOK) return;
    int e1 = g_te1[t];
    int p1 = atomicAdd(&g_cnt[e1], 1);
    g_lidx[e1 * TOK + p1] = t;
    g_lw[e1 * TOK + p1] = g_tw1[t];
    int e2 = g_te2[t];
    int p2 = atomicAdd(&g_cnt[e2], 1);
    g_lidx[e2 * TOK + p2] = t;
    g_lw[e2 * TOK + p2] = g_tw2[t];
    g_lidx[8 * TOK + t] = t;           // shared expert: identity list
    g_lw[8 * TOK + t] = 1.f;
    if (t == 0) g_cnt[8] = TOK;
}

// ---------------- input rmsnorm + act quant, all experts ----------------
// grid (TOK, NEXP)
__global__ __launch_bounds__(256) void k_xq_all(const float* __restrict__ x,
                                                const float* __restrict__ ng,
                                                const float* __restrict__ nu,
                                                const float* __restrict__ sng,
                                                const float* __restrict__ snu) {
    int e = blockIdx.y;
    int r = blockIdx.x;
    if (r >= g_cnt[e]) return;
    const float* nwg = (e < 8) ? ng + (size_t)e * HD : sng;
    const float* nwu = (e < 8) ? nu + (size_t)e * HD : snu;
    int t = g_lidx[e * TOK + r];
    __shared__ float sx[HD];
    __shared__ float red[256];
    __shared__ float bc[3];
    int tid = threadIdx.x;
    float ss = 0.f;
    const float* xr = x + (size_t)t * HD;
    for (int j = tid; j < HD; j += 256) {
        float v = clipf(xr[j], -100.f, 100.f);
        sx[j] = v;
        ss += v * v;
    }
    red[tid] = ss; __syncthreads();
    for (int o = 128; o; o >>= 1) { if (tid < o) red[tid] += red[tid + o]; __syncthreads(); }
    if (tid == 0) {
        float var = fmaxf(red[0] / (float)HD, 1e-5f);
        bc[0] = 1.f / sqrtf(var + 1e-5f);
    }
    __syncthreads();
    float rinv = bc[0];
    float mg = 0.f, mu = 0.f;
    for (int j = tid; j < HD; j += 256) {
        float xh = clipf(sx[j] * rinv, -10.f, 10.f);
        sx[j] = xh;
        float vg = clipf(nwg[j] * xh, -50.f, 50.f);
        float vu = clipf(nwu[j] * xh, -50.f, 50.f);
        mg = fmaxf(mg, fabsf(vg));
        mu = fmaxf(mu, fabsf(vu));
    }
    __syncthreads();
    red[tid] = mg; __syncthreads();
    for (int o = 128; o; o >>= 1) { if (tid < o) red[tid] = fmaxf(red[tid], red[tid + o]); __syncthreads(); }
    if (tid == 0) bc[1] = fmaxf(red[0], 1e-4f);
    __syncthreads();
    red[tid] = mu; __syncthreads();
    for (int o = 128; o; o >>= 1) { if (tid < o) red[tid] = fmaxf(red[tid], red[tid + o]); __syncthreads(); }
    if (tid == 0) bc[2] = fmaxf(red[0], 1e-4f);
    __syncthreads();
    float maxg = bc[1], maxu = bc[2];
    float scg = 127.f / maxg, scu = 127.f / maxu;
    if (tid == 0) { g_ag[e * TOK + r] = maxg / 127.f; g_au[e * TOK + r] = maxu / 127.f; }
    size_t rowoff = ((size_t)e * TOK + r) * HD;
    for (int j = tid; j < HD; j += 256) {
        float xh = sx[j];
        float vg = clipf(nwg[j] * xh, -50.f, 50.f);
        float vu = clipf(nwu[j] * xh, -50.f, 50.f);
        int qg = (int)rintf(vg * scg); qg = max(-128, min(127, qg));
        int qu = (int)rintf(vu * scu); qu = max(-128, min(127, qu));
        g_xg[rowoff + j] = (int8_t)qg;
        g_xu[rowoff + j] = (int8_t)qu;
    }
}

// ---------------- hidden rmsnorm + quant, all experts ----------------
// grid (TOK, NEXP)
__global__ __launch_bounds__(256) void k_hq_all(const float* __restrict__ nd,
                                                const float* __restrict__ snd) {
    int e = blockIdx.y;
    int r = blockIdx.x;
    if (r >= g_cnt[e]) return;
    const float* nw = (e < 8) ? nd + (size_t)e * ID : snd;
    __shared__ float sx[ID];
    __shared__ float red[256];
    __shared__ float bc[2];
    int tid = threadIdx.x;
    float ss = 0.f;
    size_t rowoff = ((size_t)e * TOK + r) * ID;
    const float* hr = g_hidden + rowoff;
    for (int j = tid; j < ID; j += 256) {
        float v = clipf(hr[j], -100.f, 100.f);
        sx[j] = v;
        ss += v * v;
    }
    red[tid] = ss; __syncthreads();
    for (int o = 128; o; o >>= 1) { if (tid < o) red[tid] += red[tid + o]; __syncthreads(); }
    if (tid == 0) {
        float var = fmaxf(red[0] / (float)ID, 1e-5f);
        bc[0] = 1.f / sqrtf(var + 1e-5f);
    }
    __syncthreads();
    float rinv = bc[0];
    float m = 0.f;
    for (int j = tid; j < ID; j += 256) {
        float xh = clipf(sx[j] * rinv, -10.f, 10.f);
        sx[j] = xh;
        float v = clipf(nw[j] * xh, -50.f, 50.f);
        m = fmaxf(m, fabsf(v));
    }
    __syncthreads();
    red[tid] = m; __syncthreads();
    for (int o = 128; o; o >>= 1) { if (tid < o) red[tid] = fmaxf(red[tid], red[tid + o]); __syncthreads(); }
    if (tid == 0) bc[1] = fmaxf(red[0], 1e-4f);
    __syncthreads();
    float maxv = bc[1];
    float sc = 127.f / maxv;
    if (tid == 0) g_ah[e * TOK + r] = maxv / 127.f;
    for (int j = tid; j < ID; j += 256) {
        float v = clipf(nw[j] * sx[j], -50.f, 50.f);
        int q = (int)rintf(v * sc); q = max(-128, min(127, q));
        g_hq[rowoff + j] = (int8_t)q;
    }
}

// ---------------- dp4a helper ----------------
__device__ __forceinline__ int dp4(int4 a, int4 b, int c) {
    c = __dp4a(a.x, b.x, c);
    c = __dp4a(a.y, b.y, c);
    c = __dp4a(a.z, b.z, c);
    c = __dp4a(a.w, b.w, c);
    return c;
}

// ---------------- GEMM 1: dual gate/up int8, silu*up -> fp32 hidden ------
// grid (TOK/64, ID/64, NEXP)
__global__ __launch_bounds__(256) void k_gemm_gu_all() {
    int e = blockIdx.z;
    int n = g_cnt[e];
    int m0 = blockIdx.x * 64;
    if (m0 >= n) return;
    int n0 = blockIdx.y * 64;

    __shared__ int4 sAg[64][4], sAu[64][4];
    __shared__ int4 sBg[4][4][17], sBu[4][4][17];

    const int4* Ag = (const int4*)(g_xg + (size_t)e * TOK * HD);
    const int4* Au = (const int4*)(g_xu + (size_t)e * TOK * HD);
    const int4* Bg = (const int4*)&g_qw[0][e][0];
    const int4* Bu = (const int4*)&g_qw[1][e][0];
    const int KI4 = HD / 16;  // 48

    int tid = threadIdx.x;
    int lr = tid >> 2, lc = tid & 3;
    int tx = tid & 15, ty = tid >> 4;
    int lbx = lr >> 2, lbj = lr & 3;

    int accg[4][4] = {}, accu[4][4] = {};
    const int4 z = make_int4(0, 0, 0, 0);

    for (int kb = 0; kb < HD / 64; kb++) {
        __syncthreads();
        int ra = m0 + lr;
        sAg[lr][lc] = (ra < n) ? Ag[(size_t)ra * KI4 + kb * 4 + lc] : z;
        sAu[lr][lc] = (ra < n) ? Au[(size_t)ra * KI4 + kb * 4 + lc] : z;
        int rb_ = n0 + lr;
        sBg[lc][lbj][lbx] = Bg[(size_t)rb_ * KI4 + kb * 4 + lc];
        sBu[lc][lbj][lbx] = Bu[(size_t)rb_ * KI4 + kb * 4 + lc];
        __syncthreads();
#pragma unroll
        for (int kk = 0; kk < 4; kk++) {
            int4 bg[4], bu[4];
#pragma unroll
            for (int j = 0; j < 4; j++) { bg[j] = sBg[kk][j][tx]; bu[j] = sBu[kk][j][tx]; }
#pragma unroll
            for (int i = 0; i < 4; i++) {
                int4 ag = sAg[ty * 4 + i][kk];
                int4 au = sAu[ty * 4 + i][kk];
#pragma unroll
                for (int j = 0; j < 4; j++) {
                    accg[i][j] = dp4(ag, bg[j], accg[i][j]);
                    accu[i][j] = dp4(au, bu[j], accu[i][j]);
                }
            }
        }
    }

    float wsg = g_wscale[0 * NEXP + e];
    float wsu = g_wscale[1 * NEXP + e];
    float* H = g_hidden + (size_t)e * TOK * ID;
#pragma unroll
    for (int i = 0; i < 4; i++) {
        int r = m0 + ty * 4 + i;
        if (r < n) {
            float sg = g_ag[e * TOK + r] * wsg;
            float su = g_au[e * TOK + r] * wsu;
#pragma unroll
            for (int j = 0; j < 4; j++) {
                int c = n0 + tx * 4 + j;
                float gg = clipf((float)accg[i][j] * sg, -20.f, 20.f);
                float uu = (float)accu[i][j] * su;
                float h = (gg / (1.f + expf(-gg))) * uu;
                H[(size_t)r * ID + c] = clipf(h, -1000.f, 1000.f);
            }
        }
    }
}

// ---------------- GEMM 2: down int8, scatter atomicAdd into out ----------
// grid (TOK/64, HD/64, NEXP)
__global__ __launch_bounds__(256) void k_gemm_d_all(float* __restrict__ out) {
    int e = blockIdx.z;
    int n = g_cnt[e];
    int m0 = blockIdx.x * 64;
    if (m0 >= n) return;
    int n0 = blockIdx.y * 64;

    __shared__ int4 sA[64][4];
    __shared__ int4 sB[4][4][17];

    const int4* A = (const int4*)(g_hq + (size_t)e * TOK * ID);
    const int4* B = (const int4*)&g_qw[2][e][0];
    const int KI4 = ID / 16;  // 128

    int tid = threadIdx.x;
    int lr = tid >> 2, lc = tid & 3;
    int tx = tid & 15, ty = tid >> 4;
    int lbx = lr >> 2, lbj = lr & 3;

    int acc[4][4] = {};
    const int4 z = make_int4(0, 0, 0, 0);

    for (int kb = 0; kb < ID / 64; kb++) {
        __syncthreads();
        int ra = m0 + lr;
        sA[lr][lc] = (ra < n) ? A[(size_t)ra * KI4 + kb * 4 + lc] : z;
        int rb_ = n0 + lr;
        sB[lc][lbj][lbx] = B[(size_t)rb_ * KI4 + kb * 4 + lc];
        __syncthreads();
#pragma unroll
        for (int kk = 0; kk < 4; kk++) {
            int4 b[4];
#pragma unroll
            for (int j = 0; j < 4; j++) b[j] = sB[kk][j][tx];
#pragma unroll
            for (int i = 0; i < 4; i++) {
                int4 a = sA[ty * 4 + i][kk];
#pragma unroll
                for (int j = 0; j < 4; j++) acc[i][j] = dp4(a, b[j], acc[i][j]);
            }
        }
    }

    float wsd = g_wscale[2 * NEXP + e];
#pragma unroll
    for (int i = 0; i < 4; i++) {
        int r = m0 + ty * 4 + i;
        if (r < n) {
            float s = g_ah[e * TOK + r] * wsd;
            int t = g_lidx[e * TOK + r];
            float lw = g_lw[e * TOK + r];
#pragma unroll
            for (int j = 0; j < 4; j++) {
                int c = n0 + tx * 4 + j;
                atomicAdd(out + (size_t)t * HD + c, lw * ((float)acc[i][j] * s));
            }
        }
    }
}

__global__ void k_clip(float* out, int n) {
    int i = blockIdx.x * blockDim.x + threadIdx.x;
    if (i < n) out[i] = clipf(out[i], -10000.f, 10000.f);
}

// ---------------- launcher ----------------
extern "C" void kernel_launch(void* const* d_in, const int* in_sizes, int n_in,
                              void* d_out, int out_size) {
    const float* x   = (const float*)d_in[0];
    const float* rw  = (const float*)d_in[1];
    const float* rb  = (const float*)d_in[2];
    const float* Wg  = (const float*)d_in[3];
    const float* Wu  = (const float*)d_in[4];
    const float* Wd  = (const float*)d_in[5];
    const float* ng  = (const float*)d_in[6];
    const float* nu  = (const float*)d_in[7];
    const float* nd  = (const float*)d_in[8];
    const float* sWg = (const float*)d_in[9];
    const float* sWu = (const float*)d_in[10];
    const float* sWd = (const float*)d_in[11];
    const float* sng = (const float*)d_in[12];
    const float* snu = (const float*)d_in[13];
    const float* snd = (const float*)d_in[14];
    float* out = (float*)d_out;

    float* logits_dst;
    if (out_size >= TOK * HD + TOK * 8) {
        logits_dst = out + (size_t)TOK * HD;
    } else {
        void* p = nullptr;
        cudaGetSymbolAddress(&p, g_logits_scratch);
        logits_dst = (float*)p;
    }

    k_zero<<<(TOK * HD + 255) / 256, 256>>>(out, TOK * HD);

    k_wred_all<<<dim3(RED_BLK, NMAT), 256>>>(Wg, Wu, Wd, sWg, sWu, sWd);
    k_wfin<<<NMAT, RED_BLK>>>();
    k_wq_all<<<dim3(NW / 4 / 256, NMAT), 256>>>(Wg, Wu, Wd, sWg, sWu, sWd);

    k_router<<<TOK, 128>>>(x, rw, rb, logits_dst);
    k_lists<<<TOK / 256, 256>>>();

    k_xq_all<<<dim3(TOK, NEXP), 256>>>(x, ng, nu, sng, snu);
    k_gemm_gu_all<<<dim3(TOK / 64, ID / 64, NEXP), 256>>>();
    k_hq_all<<<dim3(TOK, NEXP), 256>>>(nd, snd);
    k_gemm_d_all<<<dim3(TOK / 64, HD / 64, NEXP), 256>>>(out);

    k_clip<<<(TOK * HD + 255) / 256, 256>>>(out, TOK * HD);
}

// round 8
// speedup vs baseline: 1.6110x; 1.2534x over previous
#include <cuda_runtime.h>
#include <math.h>
#include <stdint.h>

// BitNet MoE layer, GB300.  R8: tensor-core int8 GEMMs (mma.sync m16n8k32
// s8s8s32), MUFU-free silu epilogue (exp2 bit-trick + Newton reciprocal),
// fp32 weight-sign threshold (R7's k_wq_all was fp64-throughput-bound).
// Hidden stays fp32 (R6 lesson).

#define TOK  8192
#define HD   768
#define ID   2048
#define NEXP 9          // 8 routed + 1 shared (slot 8)
#define NMAT 27         // kind*NEXP + e ; kind: 0=Wg 1=Wu 2=Wd
#define NW   (ID*HD)

#define RED_BLK 64

// ---------------- scratch (device globals; allocation-free) ----------------
__device__ __align__(16) int8_t g_qw[3][NEXP][NW];            // {-1,0,1}
__device__ double g_part[NMAT * RED_BLK * 2];
__device__ double g_mean[NMAT];
__device__ float  g_wscale[NMAT];
__device__ float  g_logits_scratch[TOK * 8];
__device__ int    g_te1[TOK], g_te2[TOK];
__device__ float  g_tw1[TOK], g_tw2[TOK];
__device__ int    g_cnt[NEXP];
__device__ int    g_lidx[NEXP * TOK];
__device__ float  g_lw[NEXP * TOK];
__device__ __align__(16) int8_t g_xg[(size_t)NEXP * TOK * HD];
__device__ __align__(16) int8_t g_xu[(size_t)NEXP * TOK * HD];
__device__ float  g_ag[NEXP * TOK], g_au[NEXP * TOK], g_ah[NEXP * TOK];
__device__ __align__(16) float  g_hidden[(size_t)NEXP * TOK * ID]; // fp32!
__device__ __align__(16) int8_t g_hq[(size_t)NEXP * TOK * ID];

__device__ __forceinline__ float clipf(float v, float lo, float hi) {
    return fminf(fmaxf(v, lo), hi);
}

// MUFU-free sigmoid: exp2 via rint-split + deg-6 Taylor; reciprocal via
// magic seed + 3 Newton steps.  |err| ~ 2e-7, all on fma/alu pipes.
__device__ __forceinline__ float fast_sigmoid(float g) {
    float ax = fabsf(g);
    float z  = -1.4426950408889634f * ax;   // log2(e) * (-|g|), z in [-28.9, 0]
    float nf = rintf(z);
    float f  = z - nf;                       // f in [-0.5, 0.5]
    float p  = 1.5403530e-4f;
    p = fmaf(p, f, 1.33335581e-3f);
    p = fmaf(p, f, 9.61812911e-3f);
    p = fmaf(p, f, 5.55041087e-2f);
    p = fmaf(p, f, 2.40226507e-1f);
    p = fmaf(p, f, 6.93147181e-1f);
    p = fmaf(p, f, 1.0f);
    float s = __int_as_float(((int)nf + 127) << 23);  // 2^nf (nf >= -29: normal)
    float t = p * s;                          // e^{-|g|} in (0, 1]
    float d = 1.0f + t;                       // in (1, 2]
    float r = __int_as_float(0x7EF311C3 - __float_as_int(d));
    r = r * (2.0f - d * r);
    r = r * (2.0f - d * r);
    r = r * (2.0f - d * r);                   // 1/d to fp32 accuracy
    return (g >= 0.f) ? r : 1.0f - r;
}

// ---------------- init ----------------
__global__ void k_zero(float* out, int n) {
    int i = blockIdx.x * blockDim.x + threadIdx.x;
    if (i < n) out[i] = 0.f;
    if (i < NEXP) g_cnt[i] = 0;
}

// ---------------- weight quantization ----------------
__global__ __launch_bounds__(256) void k_wred_all(
    const float* __restrict__ Wg, const float* __restrict__ Wu,
    const float* __restrict__ Wd, const float* __restrict__ sWg,
    const float* __restrict__ sWu, const float* __restrict__ sWd) {
    int m = blockIdx.y;
    int kind = m / NEXP, e = m % NEXP;
    const float* base =
        (kind == 0) ? ((e < 8) ? Wg + (size_t)e * NW : sWg)
      : (kind == 1) ? ((e < 8) ? Wu + (size_t)e * NW : sWu)
                    : ((e < 8) ? Wd + (size_t)e * NW : sWd);
    const float4* w4 = (const float4*)base;
    const int N4 = NW / 4;
    int tid = threadIdx.x;
    float s = 0.f, a = 0.f;
    for (int i = blockIdx.x * 256 + tid; i < N4; i += RED_BLK * 256) {
        float4 v = w4[i];
        s += (v.x + v.y) + (v.z + v.w);
        a += (fabsf(v.x) + fabsf(v.y)) + (fabsf(v.z) + fabsf(v.w));
    }
    __shared__ double ss[256], sa[256];
    ss[tid] = (double)s; sa[tid] = (double)a;
    __syncthreads();
    for (int o = 128; o; o >>= 1) {
        if (tid < o) { ss[tid] += ss[tid + o]; sa[tid] += sa[tid + o]; }
        __syncthreads();
    }
    if (tid == 0) {
        g_part[(m * RED_BLK + blockIdx.x) * 2 + 0] = ss[0];
        g_part[(m * RED_BLK + blockIdx.x) * 2 + 1] = sa[0];
    }
}

__global__ void k_wfin() {
    int m = blockIdx.x, tid = threadIdx.x;
    __shared__ double ss[RED_BLK], sa[RED_BLK];
    ss[tid] = g_part[(m * RED_BLK + tid) * 2 + 0];
    sa[tid] = g_part[(m * RED_BLK + tid) * 2 + 1];
    __syncthreads();
    for (int o = RED_BLK / 2; o; o >>= 1) {
        if (tid < o) { ss[tid] += ss[tid + o]; sa[tid] += sa[tid + o]; }
        __syncthreads();
    }
    if (tid == 0) {
        g_mean[m] = ss[0] / (double)NW;
        double sc = sa[0] / (double)NW;
        if (sc < 1e-8) sc = 1e-8;
        g_wscale[m] = (float)sc;
    }
}

// fp32 sign threshold (R7 version was fp64-throughput-bound: 322us -> ~70us)
__global__ __launch_bounds__(256) void k_wq_all(
    const float* __restrict__ Wg, const float* __restrict__ Wu,
    const float* __restrict__ Wd, const float* __restrict__ sWg,
    const float* __restrict__ sWu, const float* __restrict__ sWd) {
    int m = blockIdx.y;
    int kind = m / NEXP, e = m % NEXP;
    const float* base =
        (kind == 0) ? ((e < 8) ? Wg + (size_t)e * NW : sWg)
      : (kind == 1) ? ((e < 8) ? Wu + (size_t)e * NW : sWu)
                    : ((e < 8) ? Wd + (size_t)e * NW : sWd);
    int i = blockIdx.x * 256 + threadIdx.x;
    const int N4 = NW / 4;
    if (i >= N4) return;
    float mean = (float)g_mean[m];
    float4 v = ((const float4*)base)[i];
    char4 q;
    q.x = (v.x > mean) ? 1 : ((v.x < mean) ? -1 : 0);
    q.y = (v.y > mean) ? 1 : ((v.y < mean) ? -1 : 0);
    q.z = (v.z > mean) ? 1 : ((v.z < mean) ? -1 : 0);
    q.w = (v.w > mean) ? 1 : ((v.w < mean) ? -1 : 0);
    ((char4*)&g_qw[kind][e][0])[i] = q;
}

// ---------------- router ----------------
__global__ __launch_bounds__(128) void k_router(const float* __restrict__ x,
                                                const float* __restrict__ rw,
                                                const float* __restrict__ rb,
                                                float* __restrict__ logits_out) {
    int t = blockIdx.x, tid = threadIdx.x;
    const float* xr = x + (size_t)t * HD;
    float acc[8];
#pragma unroll
    for (int e = 0; e < 8; e++) acc[e] = 0.f;
    for (int h = tid; h < HD; h += 128) {
        float xv = xr[h];
#pragma unroll
        for (int e = 0; e < 8; e++) acc[e] += xv * rw[e * HD + h];
    }
    __shared__ float s[8][128];
#pragma unroll
    for (int e = 0; e < 8; e++) s[e][tid] = acc[e];
    __syncthreads();
    for (int o = 64; o; o >>= 1) {
        if (tid < o) {
#pragma unroll
            for (int e = 0; e < 8; e++) s[e][tid] += s[e][tid + o];
        }
        __syncthreads();
    }
    if (tid == 0) {
        float l[8], p[8];
        float mx = -1e30f;
#pragma unroll
        for (int e = 0; e < 8; e++) {
            l[e] = s[e][0] + rb[e];
            logits_out[t * 8 + e] = l[e];
            mx = fmaxf(mx, l[e]);
        }
        float ps = 0.f;
#pragma unroll
        for (int e = 0; e < 8; e++) { p[e] = expf(l[e] - mx); ps += p[e]; }
#pragma unroll
        for (int e = 0; e < 8; e++) p[e] /= ps;
        int i1 = 0;
#pragma unroll
        for (int e = 1; e < 8; e++) if (p[e] > p[i1]) i1 = e;
        int i2 = -1;
#pragma unroll
        for (int e = 0; e < 8; e++) {
            if (e == i1) continue;
            if (i2 < 0 || p[e] > p[i2]) i2 = e;
        }
        float den = p[i1] + p[i2] + 1e-8f;
        g_te1[t] = i1; g_te2[t] = i2;
        g_tw1[t] = p[i1] / den; g_tw2[t] = p[i2] / den;
    }
}

__global__ void k_lists() {
    int t = blockIdx.x * blockDim.x + threadIdx.x;
    if (t >= TOK) return;
    int e1 = g_te1[t];
    int p1 = atomicAdd(&g_cnt[e1], 1);
    g_lidx[e1 * TOK + p1] = t;
    g_lw[e1 * TOK + p1] = g_tw1[t];
    int e2 = g_te2[t];
    int p2 = atomicAdd(&g_cnt[e2], 1);
    g_lidx[e2 * TOK + p2] = t;
    g_lw[e2 * TOK + p2] = g_tw2[t];
    g_lidx[8 * TOK + t] = t;
    g_lw[8 * TOK + t] = 1.f;
    if (t == 0) g_cnt[8] = TOK;
}

// ---------------- input rmsnorm + act quant ----------------
__global__ __launch_bounds__(256) void k_xq_all(const float* __restrict__ x,
                                                const float* __restrict__ ng,
                                                const float* __restrict__ nu,
                                                const float* __restrict__ sng,
                                                const float* __restrict__ snu) {
    int e = blockIdx.y;
    int r = blockIdx.x;
    if (r >= g_cnt[e]) return;
    const float* nwg = (e < 8) ? ng + (size_t)e * HD : sng;
    const float* nwu = (e < 8) ? nu + (size_t)e * HD : snu;
    int t = g_lidx[e * TOK + r];
    __shared__ float sx[HD];
    __shared__ float red[256];
    __shared__ float bc[3];
    int tid = threadIdx.x;
    float ss = 0.f;
    const float* xr = x + (size_t)t * HD;
    for (int j = tid; j < HD; j += 256) {
        float v = clipf(xr[j], -100.f, 100.f);
        sx[j] = v;
        ss += v * v;
    }
    red[tid] = ss; __syncthreads();
    for (int o = 128; o; o >>= 1) { if (tid < o) red[tid] += red[tid + o]; __syncthreads(); }
    if (tid == 0) {
        float var = fmaxf(red[0] / (float)HD, 1e-5f);
        bc[0] = 1.f / sqrtf(var + 1e-5f);
    }
    __syncthreads();
    float rinv = bc[0];
    float mg = 0.f, mu = 0.f;
    for (int j = tid; j < HD; j += 256) {
        float xh = clipf(sx[j] * rinv, -10.f, 10.f);
        sx[j] = xh;
        float vg = clipf(nwg[j] * xh, -50.f, 50.f);
        float vu = clipf(nwu[j] * xh, -50.f, 50.f);
        mg = fmaxf(mg, fabsf(vg));
        mu = fmaxf(mu, fabsf(vu));
    }
    __syncthreads();
    red[tid] = mg; __syncthreads();
    for (int o = 128; o; o >>= 1) { if (tid < o) red[tid] = fmaxf(red[tid], red[tid + o]); __syncthreads(); }
    if (tid == 0) bc[1] = fmaxf(red[0], 1e-4f);
    __syncthreads();
    red[tid] = mu; __syncthreads();
    for (int o = 128; o; o >>= 1) { if (tid < o) red[tid] = fmaxf(red[tid], red[tid + o]); __syncthreads(); }
    if (tid == 0) bc[2] = fmaxf(red[0], 1e-4f);
    __syncthreads();
    float maxg = bc[1], maxu = bc[2];
    float scg = 127.f / maxg, scu = 127.f / maxu;
    if (tid == 0) { g_ag[e * TOK + r] = maxg / 127.f; g_au[e * TOK + r] = maxu / 127.f; }
    size_t rowoff = ((size_t)e * TOK + r) * HD;
    for (int j = tid; j < HD; j += 256) {
        float xh = sx[j];
        float vg = clipf(nwg[j] * xh, -50.f, 50.f);
        float vu = clipf(nwu[j] * xh, -50.f, 50.f);
        int qg = (int)rintf(vg * scg); qg = max(-128, min(127, qg));
        int qu = (int)rintf(vu * scu); qu = max(-128, min(127, qu));
        g_xg[rowoff + j] = (int8_t)qg;
        g_xu[rowoff + j] = (int8_t)qu;
    }
}

// ---------------- hidden rmsnorm + quant ----------------
__global__ __launch_bounds__(256) void k_hq_all(const float* __restrict__ nd,
                                                const float* __restrict__ snd) {
    int e = blockIdx.y;
    int r = blockIdx.x;
    if (r >= g_cnt[e]) return;
    const float* nw = (e < 8) ? nd + (size_t)e * ID : snd;
    __shared__ float sx[ID];
    __shared__ float red[256];
    __shared__ float bc[2];
    int tid = threadIdx.x;
    float ss = 0.f;
    size_t rowoff = ((size_t)e * TOK + r) * ID;
    const float* hr = g_hidden + rowoff;
    for (int j = tid; j < ID; j += 256) {
        float v = clipf(hr[j], -100.f, 100.f);
        sx[j] = v;
        ss += v * v;
    }
    red[tid] = ss; __syncthreads();
    for (int o = 128; o; o >>= 1) { if (tid < o) red[tid] += red[tid + o]; __syncthreads(); }
    if (tid == 0) {
        float var = fmaxf(red[0] / (float)ID, 1e-5f);
        bc[0] = 1.f / sqrtf(var + 1e-5f);
    }
    __syncthreads();
    float rinv = bc[0];
    float m = 0.f;
    for (int j = tid; j < ID; j += 256) {
        float xh = clipf(sx[j] * rinv, -10.f, 10.f);
        sx[j] = xh;
        float v = clipf(nw[j] * xh, -50.f, 50.f);
        m = fmaxf(m, fabsf(v));
    }
    __syncthreads();
    red[tid] = m; __syncthreads();
    for (int o = 128; o; o >>= 1) { if (tid < o) red[tid] = fmaxf(red[tid], red[tid + o]); __syncthreads(); }
    if (tid == 0) bc[1] = fmaxf(red[0], 1e-4f);
    __syncthreads();
    float maxv = bc[1];
    float sc = 127.f / maxv;
    if (tid == 0) g_ah[e * TOK + r] = maxv / 127.f;
    for (int j = tid; j < ID; j += 256) {
        float v = clipf(nw[j] * sx[j], -50.f, 50.f);
        int q = (int)rintf(v * sc); q = max(-128, min(127, q));
        g_hq[rowoff + j] = (int8_t)q;
    }
}

// ---------------- mma.sync helper ----------------
__device__ __forceinline__ void mma_s8(int* c, const int* a, const int* b) {
    asm volatile(
        "mma.sync.aligned.m16n8k32.row.col.s32.s8.s8.s32 "
        "{%0,%1,%2,%3}, {%4,%5,%6,%7}, {%8,%9}, {%0,%1,%2,%3};"
        : "+r"(c[0]), "+r"(c[1]), "+r"(c[2]), "+r"(c[3])
        : "r"(a[0]), "r"(a[1]), "r"(a[2]), "r"(a[3]), "r"(b[0]), "r"(b[1]));
}

// A-fragment: rows (lane>>2)+{0,8}, k bytes (lane&3)*4 + {0,16}
__device__ __forceinline__ void load_a_frag(int* a, const int8_t* smem_row0,
                                            int stride, int lane) {
    const int8_t* p = smem_row0 + (lane >> 2) * stride + (lane & 3) * 4;
    a[0] = *(const int*)(p);
    a[1] = *(const int*)(p + 8 * stride);
    a[2] = *(const int*)(p + 16);
    a[3] = *(const int*)(p + 8 * stride + 16);
}
// B-fragment: col-row (lane>>2), k bytes (lane&3)*4 + {0,16}
__device__ __forceinline__ void load_b_frag(int* b, const int8_t* smem_row0,
                                            int stride, int lane) {
    const int8_t* p = smem_row0 + (lane >> 2) * stride + (lane & 3) * 4;
    b[0] = *(const int*)(p);
    b[1] = *(const int*)(p + 16);
}

// ---------------- GEMM 1: gate+up tensor-core, silu*up -> fp32 hidden ----
// grid (TOK/128, ID/64, NEXP), 128 threads (4 warps, 2M x 2N, warp 64x32)
#define SMS 80   // smem row stride (bytes); 80 = 5*16, conflict-free & 16B-aligned
__global__ __launch_bounds__(128) void k_gemm_gu_mma() {
    int e = blockIdx.z;
    int n = g_cnt[e];
    int m0 = blockIdx.x * 128;
    if (m0 >= n) return;
    int n0 = blockIdx.y * 64;

    __shared__ int8_t sAg[128][SMS], sAu[128][SMS];
    __shared__ int8_t sBg[64][SMS],  sBu[64][SMS];

    const int4* Ag4 = (const int4*)(g_xg + (size_t)e * TOK * HD);
    const int4* Au4 = (const int4*)(g_xu + (size_t)e * TOK * HD);
    const int4* Bg4 = (const int4*)&g_qw[0][e][0];
    const int4* Bu4 = (const int4*)&g_qw[1][e][0];
    const int KA4 = HD / 16;  // 48 int4 per A/B row

    int tid = threadIdx.x;
    int warp = tid >> 5, lane = tid & 31;
    int wm = (warp >> 1) * 64;     // warp M offset within block
    int wn = (warp & 1) * 32;      // warp N offset within block

    int cg[4][4][4];  // [mt][nt][frag]
    int cu[4][4][4];
#pragma unroll
    for (int i = 0; i < 4; i++)
#pragma unroll
        for (int j = 0; j < 4; j++)
#pragma unroll
            for (int k = 0; k < 4; k++) { cg[i][j][k] = 0; cu[i][j][k] = 0; }

    const int4 z4 = make_int4(0, 0, 0, 0);

    for (int kb = 0; kb < HD / 64; kb++) {
        __syncthreads();
        // load A tiles (128 rows x 64B), both matrices
        for (int i = tid; i < 512; i += 128) {
            int row = i >> 2, seg = i & 3;
            int gr = m0 + row;
            int4 vg = (gr < n) ? Ag4[(size_t)gr * KA4 + kb * 4 + seg] : z4;
            int4 vu = (gr < n) ? Au4[(size_t)gr * KA4 + kb * 4 + seg] : z4;
            *(int4*)&sAg[row][seg * 16] = vg;
            *(int4*)&sAu[row][seg * 16] = vu;
        }
        // load B tiles (64 rows x 64B), both matrices
        for (int i = tid; i < 256; i += 128) {
            int row = i >> 2, seg = i & 3;
            int br = n0 + row;
            *(int4*)&sBg[row][seg * 16] = Bg4[(size_t)br * KA4 + kb * 4 + seg];
            *(int4*)&sBu[row][seg * 16] = Bu4[(size_t)br * KA4 + kb * 4 + seg];
        }
        __syncthreads();
#pragma unroll
        for (int ks = 0; ks < 2; ks++) {
            int bg[4][2], bu[4][2];
#pragma unroll
            for (int nt = 0; nt < 4; nt++) {
                load_b_frag(bg[nt], &sBg[wn + nt * 8][ks * 32], SMS, lane);
                load_b_frag(bu[nt], &sBu[wn + nt * 8][ks * 32], SMS, lane);
            }
#pragma unroll
            for (int mt = 0; mt < 4; mt++) {
                int ag[4], au[4];
                load_a_frag(ag, &sAg[wm + mt * 16][ks * 32], SMS, lane);
                load_a_frag(au, &sAu[wm + mt * 16][ks * 32], SMS, lane);
#pragma unroll
                for (int nt = 0; nt < 4; nt++) {
                    mma_s8(cg[mt][nt], ag, bg[nt]);
                    mma_s8(cu[mt][nt], au, bu[nt]);
                }
            }
        }
    }

    // epilogue: silu(gate)*up -> hidden (fp32)
    float wsg = g_wscale[0 * NEXP + e];
    float wsu = g_wscale[1 * NEXP + e];
    float* H = g_hidden + (size_t)e * TOK * ID;
#pragma unroll
    for (int mt = 0; mt < 4; mt++) {
        int r0 = m0 + wm + mt * 16 + (lane >> 2);
#pragma unroll
        for (int half = 0; half < 2; half++) {
            int r = r0 + half * 8;
            if (r >= n) continue;
            float sg = g_ag[e * TOK + r] * wsg;
            float su = g_au[e * TOK + r] * wsu;
            float* Hr = H + (size_t)r * ID;
#pragma unroll
            for (int nt = 0; nt < 4; nt++) {
                int c = n0 + wn + nt * 8 + (lane & 3) * 2;
#pragma unroll
                for (int cc = 0; cc < 2; cc++) {
                    int gi = cg[mt][nt][half * 2 + cc];
                    int ui = cu[mt][nt][half * 2 + cc];
                    float gg = clipf((float)gi * sg, -20.f, 20.f);
                    float uu = (float)ui * su;
                    float h = gg * fast_sigmoid(gg) * uu;
                    Hr[c + cc] = clipf(h, -1000.f, 1000.f);
                }
            }
        }
    }
}

// ---------------- GEMM 2: down tensor-core, scatter atomicAdd -------------
// grid (TOK/128, HD/64, NEXP), 128 threads, block 128x64, warp 64x32, K=2048
__global__ __launch_bounds__(128) void k_gemm_d_mma(float* __restrict__ out) {
    int e = blockIdx.z;
    int n = g_cnt[e];
    int m0 = blockIdx.x * 128;
    if (m0 >= n) return;
    int n0 = blockIdx.y * 64;

    __shared__ int8_t sA[128][SMS];
    __shared__ int8_t sB[64][SMS];

    const int4* A4 = (const int4*)(g_hq + (size_t)e * TOK * ID);
    const int4* B4 = (const int4*)&g_qw[2][e][0];
    const int KA4 = ID / 16;  // 128 int4 per row

    int tid = threadIdx.x;
    int warp = tid >> 5, lane = tid & 31;
    int wm = (warp >> 1) * 64;
    int wn = (warp & 1) * 32;

    int acc[4][4][4];
#pragma unroll
    for (int i = 0; i < 4; i++)
#pragma unroll
        for (int j = 0; j < 4; j++)
#pragma unroll
            for (int k = 0; k < 4; k++) acc[i][j][k] = 0;

    const int4 z4 = make_int4(0, 0, 0, 0);

    for (int kb = 0; kb < ID / 64; kb++) {
        __syncthreads();
        for (int i = tid; i < 512; i += 128) {
            int row = i >> 2, seg = i & 3;
            int gr = m0 + row;
            int4 v = (gr < n) ? A4[(size_t)gr * KA4 + kb * 4 + seg] : z4;
            *(int4*)&sA[row][seg * 16] = v;
        }
        for (int i = tid; i < 256; i += 128) {
            int row = i >> 2, seg = i & 3;
            int br = n0 + row;
            *(int4*)&sB[row][seg * 16] = B4[(size_t)br * KA4 + kb * 4 + seg];
        }
        __syncthreads();
#pragma unroll
        for (int ks = 0; ks < 2; ks++) {
            int b[4][2];
#pragma unroll
            for (int nt = 0; nt < 4; nt++)
                load_b_frag(b[nt], &sB[wn + nt * 8][ks * 32], SMS, lane);
#pragma unroll
            for (int mt = 0; mt < 4; mt++) {
                int a[4];
                load_a_frag(a, &sA[wm + mt * 16][ks * 32], SMS, lane);
#pragma unroll
                for (int nt = 0; nt < 4; nt++)
                    mma_s8(acc[mt][nt], a, b[nt]);
            }
        }
    }

    float wsd = g_wscale[2 * NEXP + e];
#pragma unroll
    for (int mt = 0; mt < 4; mt++) {
        int r0 = m0 + wm + mt * 16 + (lane >> 2);
#pragma unroll
        for (int half = 0; half < 2; half++) {
            int r = r0 + half * 8;
            if (r >= n) continue;
            float s = g_ah[e * TOK + r] * wsd;
            int t = g_lidx[e * TOK + r];
            float lw = g_lw[e * TOK + r];
            float* outr = out + (size_t)t * HD;
#pragma unroll
            for (int nt = 0; nt < 4; nt++) {
                int c = n0 + wn + nt * 8 + (lane & 3) * 2;
#pragma unroll
                for (int cc = 0; cc < 2; cc++) {
                    float y = lw * ((float)acc[mt][nt][half * 2 + cc] * s);
                    atomicAdd(outr + c + cc, y);
                }
            }
        }
    }
}

__global__ void k_clip(float* out, int n) {
    int i = blockIdx.x * blockDim.x + threadIdx.x;
    if (i < n) out[i] = clipf(out[i], -10000.f, 10000.f);
}

// ---------------- launcher ----------------
extern "C" void kernel_launch(void* const* d_in, const int* in_sizes, int n_in,
                              void* d_out, int out_size) {
    const float* x   = (const float*)d_in[0];
    const float* rw  = (const float*)d_in[1];
    const float* rb  = (const float*)d_in[2];
    const float* Wg  = (const float*)d_in[3];
    const float* Wu  = (const float*)d_in[4];
    const float* Wd  = (const float*)d_in[5];
    const float* ng  = (const float*)d_in[6];
    const float* nu  = (const float*)d_in[7];
    const float* nd  = (const float*)d_in[8];
    const float* sWg = (const float*)d_in[9];
    const float* sWu = (const float*)d_in[10];
    const float* sWd = (const float*)d_in[11];
    const float* sng = (const float*)d_in[12];
    const float* snu = (const float*)d_in[13];
    const float* snd = (const float*)d_in[14];
    float* out = (float*)d_out;

    float* logits_dst;
    if (out_size >= TOK * HD + TOK * 8) {
        logits_dst = out + (size_t)TOK * HD;
    } else {
        void* p = nullptr;
        cudaGetSymbolAddress(&p, g_logits_scratch);
        logits_dst = (float*)p;
    }

    k_zero<<<(TOK * HD + 255) / 256, 256>>>(out, TOK * HD);

    k_wred_all<<<dim3(RED_BLK, NMAT), 256>>>(Wg, Wu, Wd, sWg, sWu, sWd);
    k_wfin<<<NMAT, RED_BLK>>>();
    k_wq_all<<<dim3(NW / 4 / 256, NMAT), 256>>>(Wg, Wu, Wd, sWg, sWu, sWd);

    k_router<<<TOK, 128>>>(x, rw, rb, logits_dst);
    k_lists<<<TOK / 256, 256>>>();

    k_xq_all<<<dim3(TOK, NEXP), 256>>>(x, ng, nu, sng, snu);
    k_gemm_gu_mma<<<dim3(TOK / 128, ID / 64, NEXP), 128>>>();
    k_hq_all<<<dim3(TOK, NEXP), 256>>>(nd, snd);
    k_gemm_d_mma<<<dim3(TOK / 128, HD / 64, NEXP), 128>>>(out);

    k_clip<<<(TOK * HD + 255) / 256, 256>>>(out, TOK * HD);
}

// round 10
// speedup vs baseline: 1.8623x; 1.1560x over previous
#include <cuda_runtime.h>
#include <math.h>
#include <stdint.h>

// BitNet MoE layer, GB300.  R10: tcgen05 is OFF THE TABLE (harness compiles
// .target sm_103, no 'a' features).  Base = R8 (mma.sync s8 GEMM, proven).
// Changes: warp-per-row xq/hq (shuffle reductions), cp.async double-buffered
// GEMM tiles, launch order puts k_gemm_gu_mma at position 6 for ncu capture.

#define TOK  8192
#define HD   768
#define ID   2048
#define NEXP 9          // 8 routed + 1 shared (slot 8)
#define NMAT 27
#define NW   (ID*HD)
#define RED_BLK 64

// ---------------- scratch (device globals; allocation-free) ----------------
__device__ __align__(16) int8_t g_qw[3][NEXP][NW];            // {-1,0,1}
__device__ double g_part[NMAT * RED_BLK * 2];
__device__ double g_mean[NMAT];
__device__ float  g_wscale[NMAT];
__device__ float  g_logits_scratch[TOK * 8];
__device__ int    g_cnt[NEXP];
__device__ int    g_lidx[NEXP * TOK];
__device__ float  g_lw[NEXP * TOK];
__device__ __align__(16) int8_t g_xg[(size_t)NEXP * TOK * HD];
__device__ __align__(16) int8_t g_xu[(size_t)NEXP * TOK * HD];
__device__ float  g_ag[NEXP * TOK], g_au[NEXP * TOK], g_ah[NEXP * TOK];
__device__ __align__(16) float  g_hidden[(size_t)NEXP * TOK * ID]; // fp32
__device__ __align__(16) int8_t g_hq[(size_t)NEXP * TOK * ID];

__device__ __forceinline__ float clipf(float v, float lo, float hi) {
    return fminf(fmaxf(v, lo), hi);
}

__device__ __forceinline__ float fast_sigmoid(float g) {
    float ax = fabsf(g);
    float z  = -1.4426950408889634f * ax;
    float nf = rintf(z);
    float f  = z - nf;
    float p  = 1.5403530e-4f;
    p = fmaf(p, f, 1.33335581e-3f);
    p = fmaf(p, f, 9.61812911e-3f);
    p = fmaf(p, f, 5.55041087e-2f);
    p = fmaf(p, f, 2.40226507e-1f);
    p = fmaf(p, f, 6.93147181e-1f);
    p = fmaf(p, f, 1.0f);
    float s = __int_as_float(((int)nf + 127) << 23);
    float t = p * s;
    float d = 1.0f + t;
    float r = __int_as_float(0x7EF311C3 - __float_as_int(d));
    r = r * (2.0f - d * r);
    r = r * (2.0f - d * r);
    r = r * (2.0f - d * r);
    return (g >= 0.f) ? r : 1.0f - r;
}

__device__ __forceinline__ uint32_t smem_u32(const void* p) {
    uint32_t a;
    asm("{ .reg .u64 t; cvta.to.shared.u64 t, %1; cvt.u32.u64 %0, t; }"
        : "=r"(a) : "l"(p));
    return a;
}
__device__ __forceinline__ void cpa16(uint32_t dst, const void* src) {
    asm volatile("cp.async.cg.shared.global [%0], [%1], 16;"
                 :: "r"(dst), "l"(src) : "memory");
}
#define CP_COMMIT() asm volatile("cp.async.commit_group;" ::: "memory")
#define CP_WAIT1()  asm volatile("cp.async.wait_group 1;" ::: "memory")

// ---------------- weight quantization ----------------
__global__ __launch_bounds__(256) void k_wred_all(
    const float* __restrict__ Wg, const float* __restrict__ Wu,
    const float* __restrict__ Wd, const float* __restrict__ sWg,
    const float* __restrict__ sWu, const float* __restrict__ sWd) {
    int m = blockIdx.y;
    int kind = m / NEXP, e = m % NEXP;
    const float* base =
        (kind == 0) ? ((e < 8) ? Wg + (size_t)e * NW : sWg)
      : (kind == 1) ? ((e < 8) ? Wu + (size_t)e * NW : sWu)
                    : ((e < 8) ? Wd + (size_t)e * NW : sWd);
    const float4* w4 = (const float4*)base;
    const int N4 = NW / 4;
    int tid = threadIdx.x;
    if (blockIdx.x == 0 && m == 0 && tid < NEXP) g_cnt[tid] = 0;  // fused init
    float s = 0.f, a = 0.f;
    for (int i = blockIdx.x * 256 + tid; i < N4; i += RED_BLK * 256) {
        float4 v = w4[i];
        s += (v.x + v.y) + (v.z + v.w);
        a += (fabsf(v.x) + fabsf(v.y)) + (fabsf(v.z) + fabsf(v.w));
    }
    __shared__ double ss[256], sa[256];
    ss[tid] = (double)s; sa[tid] = (double)a;
    __syncthreads();
    for (int o = 128; o; o >>= 1) {
        if (tid < o) { ss[tid] += ss[tid + o]; sa[tid] += sa[tid + o]; }
        __syncthreads();
    }
    if (tid == 0) {
        g_part[(m * RED_BLK + blockIdx.x) * 2 + 0] = ss[0];
        g_part[(m * RED_BLK + blockIdx.x) * 2 + 1] = sa[0];
    }
}

__global__ void k_wfin() {
    int m = blockIdx.x, tid = threadIdx.x;   // RED_BLK threads
    __shared__ double ss[RED_BLK], sa[RED_BLK];
    ss[tid] = g_part[(m * RED_BLK + tid) * 2 + 0];
    sa[tid] = g_part[(m * RED_BLK + tid) * 2 + 1];
    __syncthreads();
    for (int o = RED_BLK / 2; o; o >>= 1) {
        if (tid < o) { ss[tid] += ss[tid + o]; sa[tid] += sa[tid + o]; }
        __syncthreads();
    }
    if (tid == 0) {
        g_mean[m] = ss[0] / (double)NW;
        double sc = sa[0] / (double)NW;
        if (sc < 1e-8) sc = 1e-8;
        g_wscale[m] = (float)sc;
    }
}

__global__ __launch_bounds__(256) void k_wq_all(
    const float* __restrict__ Wg, const float* __restrict__ Wu,
    const float* __restrict__ Wd, const float* __restrict__ sWg,
    const float* __restrict__ sWu, const float* __restrict__ sWd) {
    int m = blockIdx.y;
    int kind = m / NEXP, e = m % NEXP;
    const float* base =
        (kind == 0) ? ((e < 8) ? Wg + (size_t)e * NW : sWg)
      : (kind == 1) ? ((e < 8) ? Wu + (size_t)e * NW : sWu)
                    : ((e < 8) ? Wd + (size_t)e * NW : sWd);
    int i = blockIdx.x * 256 + threadIdx.x;
    const int N4 = NW / 4;
    if (i >= N4) return;
    float mean = (float)g_mean[m];
    float4 v = ((const float4*)base)[i];
    char4 q;
    q.x = (v.x > mean) ? 1 : ((v.x < mean) ? -1 : 0);
    q.y = (v.y > mean) ? 1 : ((v.y < mean) ? -1 : 0);
    q.z = (v.z > mean) ? 1 : ((v.z < mean) ? -1 : 0);
    q.w = (v.w > mean) ? 1 : ((v.w < mean) ? -1 : 0);
    ((char4*)&g_qw[kind][e][0])[i] = q;
}

// ---------------- router + top2 lists + out-zeroing (fused) ----------------
__global__ __launch_bounds__(128) void k_router_lists(const float* __restrict__ x,
                                                      const float* __restrict__ rw,
                                                      const float* __restrict__ rb,
                                                      float* __restrict__ logits_out,
                                                      float* __restrict__ out) {
    int t = blockIdx.x, tid = threadIdx.x;
    for (int j = tid; j < HD; j += 128) out[(size_t)t * HD + j] = 0.f;
    const float* xr = x + (size_t)t * HD;
    float acc[8];
#pragma unroll
    for (int e = 0; e < 8; e++) acc[e] = 0.f;
    for (int h = tid; h < HD; h += 128) {
        float xv = xr[h];
#pragma unroll
        for (int e = 0; e < 8; e++) acc[e] += xv * rw[e * HD + h];
    }
    __shared__ float s[8][128];
#pragma unroll
    for (int e = 0; e < 8; e++) s[e][tid] = acc[e];
    __syncthreads();
    for (int o = 64; o; o >>= 1) {
        if (tid < o) {
#pragma unroll
            for (int e = 0; e < 8; e++) s[e][tid] += s[e][tid + o];
        }
        __syncthreads();
    }
    if (tid == 0) {
        float l[8], p[8];
        float mx = -1e30f;
#pragma unroll
        for (int e = 0; e < 8; e++) {
            l[e] = s[e][0] + rb[e];
            logits_out[t * 8 + e] = l[e];
            mx = fmaxf(mx, l[e]);
        }
        float ps = 0.f;
#pragma unroll
        for (int e = 0; e < 8; e++) { p[e] = expf(l[e] - mx); ps += p[e]; }
#pragma unroll
        for (int e = 0; e < 8; e++) p[e] /= ps;
        int i1 = 0;
#pragma unroll
        for (int e = 1; e < 8; e++) if (p[e] > p[i1]) i1 = e;
        int i2 = -1;
#pragma unroll
        for (int e = 0; e < 8; e++) {
            if (e == i1) continue;
            if (i2 < 0 || p[e] > p[i2]) i2 = e;
        }
        float den = p[i1] + p[i2] + 1e-8f;
        int p1 = atomicAdd(&g_cnt[i1], 1);
        g_lidx[i1 * TOK + p1] = t;
        g_lw[i1 * TOK + p1] = p[i1] / den;
        int p2 = atomicAdd(&g_cnt[i2], 1);
        g_lidx[i2 * TOK + p2] = t;
        g_lw[i2 * TOK + p2] = p[i2] / den;
        g_lidx[8 * TOK + t] = t;
        g_lw[8 * TOK + t] = 1.f;
        if (t == 0) g_cnt[8] = TOK;
    }
}

// ---------------- input rmsnorm + act quant: warp per row ----------------
// grid (TOK/8, NEXP), 256 threads = 8 warps, warp w -> row blockIdx.x*8+w
__global__ __launch_bounds__(256) void k_xq_all(const float* __restrict__ x,
                                                const float* __restrict__ ng,
                                                const float* __restrict__ nu,
                                                const float* __restrict__ sng,
                                                const float* __restrict__ snu) {
    int e = blockIdx.y;
    int wid = threadIdx.x >> 5, lane = threadIdx.x & 31;
    int r = blockIdx.x * 8 + wid;
    if (r >= g_cnt[e]) return;
    const float* nwg = (e < 8) ? ng + (size_t)e * HD : sng;
    const float* nwu = (e < 8) ? nu + (size_t)e * HD : snu;
    int t = g_lidx[e * TOK + r];
    const float4* xr4 = (const float4*)(x + (size_t)t * HD);
    const float4* ng4 = (const float4*)nwg;
    const float4* nu4 = (const float4*)nwu;

    float v[24], gw[24], uw[24];
    float ssum = 0.f;
#pragma unroll
    for (int i = 0; i < 6; i++) {
        float4 w = xr4[lane + i * 32];
        float4 a = ng4[lane + i * 32];
        float4 b = nu4[lane + i * 32];
        float c0 = clipf(w.x, -100.f, 100.f), c1 = clipf(w.y, -100.f, 100.f);
        float c2 = clipf(w.z, -100.f, 100.f), c3 = clipf(w.w, -100.f, 100.f);
        v[i*4+0] = c0; v[i*4+1] = c1; v[i*4+2] = c2; v[i*4+3] = c3;
        ssum += c0*c0 + c1*c1 + c2*c2 + c3*c3;
        gw[i*4+0] = a.x; gw[i*4+1] = a.y; gw[i*4+2] = a.z; gw[i*4+3] = a.w;
        uw[i*4+0] = b.x; uw[i*4+1] = b.y; uw[i*4+2] = b.z; uw[i*4+3] = b.w;
    }
#pragma unroll
    for (int o = 16; o; o >>= 1) ssum += __shfl_xor_sync(0xFFFFFFFFu, ssum, o);
    float var = fmaxf(ssum / (float)HD, 1e-5f);
    float rinv = 1.f / sqrtf(var + 1e-5f);

    float mg = 0.f, mu = 0.f;
#pragma unroll
    for (int i = 0; i < 24; i++) {
        float xh = clipf(v[i] * rinv, -10.f, 10.f);
        float vg = clipf(gw[i] * xh, -50.f, 50.f);
        float vu = clipf(uw[i] * xh, -50.f, 50.f);
        gw[i] = vg; uw[i] = vu;
        mg = fmaxf(mg, fabsf(vg));
        mu = fmaxf(mu, fabsf(vu));
    }
#pragma unroll
    for (int o = 16; o; o >>= 1) {
        mg = fmaxf(mg, __shfl_xor_sync(0xFFFFFFFFu, mg, o));
        mu = fmaxf(mu, __shfl_xor_sync(0xFFFFFFFFu, mu, o));
    }
    mg = fmaxf(mg, 1e-4f); mu = fmaxf(mu, 1e-4f);
    if (lane == 0) { g_ag[e * TOK + r] = mg / 127.f; g_au[e * TOK + r] = mu / 127.f; }
    float scg = 127.f / mg, scu = 127.f / mu;
    size_t rowoff = ((size_t)e * TOK + r) * HD;
    char4* og = (char4*)(g_xg + rowoff);
    char4* ou = (char4*)(g_xu + rowoff);
#pragma unroll
    for (int i = 0; i < 6; i++) {
        char4 qg, qu;
        int q;
        q = (int)rintf(gw[i*4+0] * scg); qg.x = (char)max(-128, min(127, q));
        q = (int)rintf(gw[i*4+1] * scg); qg.y = (char)max(-128, min(127, q));
        q = (int)rintf(gw[i*4+2] * scg); qg.z = (char)max(-128, min(127, q));
        q = (int)rintf(gw[i*4+3] * scg); qg.w = (char)max(-128, min(127, q));
        q = (int)rintf(uw[i*4+0] * scu); qu.x = (char)max(-128, min(127, q));
        q = (int)rintf(uw[i*4+1] * scu); qu.y = (char)max(-128, min(127, q));
        q = (int)rintf(uw[i*4+2] * scu); qu.z = (char)max(-128, min(127, q));
        q = (int)rintf(uw[i*4+3] * scu); qu.w = (char)max(-128, min(127, q));
        og[lane + i * 32] = qg;
        ou[lane + i * 32] = qu;
    }
}

// ---------------- hidden rmsnorm + quant: warp per row ----------------
__global__ __launch_bounds__(256) void k_hq_all(const float* __restrict__ nd,
                                                const float* __restrict__ snd) {
    int e = blockIdx.y;
    int wid = threadIdx.x >> 5, lane = threadIdx.x & 31;
    int r = blockIdx.x * 8 + wid;
    if (r >= g_cnt[e]) return;
    const float* nw = (e < 8) ? nd + (size_t)e * ID : snd;
    size_t rowoff = ((size_t)e * TOK + r) * ID;
    const float4* hr4 = (const float4*)(g_hidden + rowoff);
    const float4* nw4 = (const float4*)nw;

    float v[64];
    float ssum = 0.f;
#pragma unroll
    for (int i = 0; i < 16; i++) {
        float4 w = hr4[lane + i * 32];
        float c0 = clipf(w.x, -100.f, 100.f), c1 = clipf(w.y, -100.f, 100.f);
        float c2 = clipf(w.z, -100.f, 100.f), c3 = clipf(w.w, -100.f, 100.f);
        v[i*4+0] = c0; v[i*4+1] = c1; v[i*4+2] = c2; v[i*4+3] = c3;
        ssum += c0*c0 + c1*c1 + c2*c2 + c3*c3;
    }
#pragma unroll
    for (int o = 16; o; o >>= 1) ssum += __shfl_xor_sync(0xFFFFFFFFu, ssum, o);
    float var = fmaxf(ssum / (float)ID, 1e-5f);
    float rinv = 1.f / sqrtf(var + 1e-5f);

    float m = 0.f;
#pragma unroll
    for (int i = 0; i < 16; i++) {
        float4 a = nw4[lane + i * 32];
        float xh0 = clipf(v[i*4+0] * rinv, -10.f, 10.f);
        float xh1 = clipf(v[i*4+1] * rinv, -10.f, 10.f);
        float xh2 = clipf(v[i*4+2] * rinv, -10.f, 10.f);
        float xh3 = clipf(v[i*4+3] * rinv, -10.f, 10.f);
        v[i*4+0] = clipf(a.x * xh0, -50.f, 50.f);
        v[i*4+1] = clipf(a.y * xh1, -50.f, 50.f);
        v[i*4+2] = clipf(a.z * xh2, -50.f, 50.f);
        v[i*4+3] = clipf(a.w * xh3, -50.f, 50.f);
        m = fmaxf(m, fmaxf(fmaxf(fabsf(v[i*4+0]), fabsf(v[i*4+1])),
                           fmaxf(fabsf(v[i*4+2]), fabsf(v[i*4+3]))));
    }
#pragma unroll
    for (int o = 16; o; o >>= 1) m = fmaxf(m, __shfl_xor_sync(0xFFFFFFFFu, m, o));
    m = fmaxf(m, 1e-4f);
    if (lane == 0) g_ah[e * TOK + r] = m / 127.f;
    float sc = 127.f / m;
    char4* oq = (char4*)(g_hq + rowoff);
#pragma unroll
    for (int i = 0; i < 16; i++) {
        char4 q4;
        int q;
        q = (int)rintf(v[i*4+0] * sc); q4.x = (char)max(-128, min(127, q));
        q = (int)rintf(v[i*4+1] * sc); q4.y = (char)max(-128, min(127, q));
        q = (int)rintf(v[i*4+2] * sc); q4.z = (char)max(-128, min(127, q));
        q = (int)rintf(v[i*4+3] * sc); q4.w = (char)max(-128, min(127, q));
        oq[lane + i * 32] = q4;
    }
}

// ---------------- mma.sync helpers (R8, proven) ----------------
__device__ __forceinline__ void mma_s8(int* c, const int* a, const int* b) {
    asm volatile(
        "mma.sync.aligned.m16n8k32.row.col.s32.s8.s8.s32 "
        "{%0,%1,%2,%3}, {%4,%5,%6,%7}, {%8,%9}, {%0,%1,%2,%3};"
        : "+r"(c[0]), "+r"(c[1]), "+r"(c[2]), "+r"(c[3])
        : "r"(a[0]), "r"(a[1]), "r"(a[2]), "r"(a[3]), "r"(b[0]), "r"(b[1]));
}
__device__ __forceinline__ void load_a_frag(int* a, const int8_t* smem_row0,
                                            int stride, int lane) {
    const int8_t* p = smem_row0 + (lane >> 2) * stride + (lane & 3) * 4;
    a[0] = *(const int*)(p);
    a[1] = *(const int*)(p + 8 * stride);
    a[2] = *(const int*)(p + 16);
    a[3] = *(const int*)(p + 8 * stride + 16);
}
__device__ __forceinline__ void load_b_frag(int* b, const int8_t* smem_row0,
                                            int stride, int lane) {
    const int8_t* p = smem_row0 + (lane >> 2) * stride + (lane & 3) * 4;
    b[0] = *(const int*)(p);
    b[1] = *(const int*)(p + 16);
}

// ---------------- GEMM 1: gate+up, cp.async double-buffered --------------
// grid (TOK/128, ID/64, NEXP), 128 threads; dyn smem 2 stages x 30720 B.
#define GU_STG 30720
#define GU_SMEM (2 * GU_STG)
__global__ __launch_bounds__(128) void k_gemm_gu_mma() {
    int e = blockIdx.z;
    int n = g_cnt[e];
    int m0 = blockIdx.x * 128;
    if (m0 >= n) return;
    int n0 = blockIdx.y * 64;

    extern __shared__ __align__(16) uint8_t dsm[];
    uint32_t sb = smem_u32(dsm);

    const int4* Ag4 = (const int4*)(g_xg + (size_t)e * TOK * HD);
    const int4* Au4 = (const int4*)(g_xu + (size_t)e * TOK * HD);
    const int4* Bg4 = (const int4*)&g_qw[0][e][0];
    const int4* Bu4 = (const int4*)&g_qw[1][e][0];
    const int KI4 = HD / 16;  // 48

    int tid = threadIdx.x;
    int warp = tid >> 5, lane = tid & 31;
    int wm = (warp >> 1) * 64;
    int wn = (warp & 1) * 32;

    int cg[4][4][4] = {};
    int cu[4][4][4] = {};

#define GU_ISSUE(kb_) do {                                                    \
        int st_ = (kb_) & 1; uint32_t b_ = sb + st_ * GU_STG;                 \
        for (int i = tid; i < 512; i += 128) {                                \
            int row_ = i >> 2, seg_ = i & 3;                                  \
            int grc_ = min(m0 + row_, n - 1);                                 \
            uint32_t d_ = b_ + row_ * 80 + seg_ * 16;                         \
            cpa16(d_,         Ag4 + (size_t)grc_ * KI4 + (kb_) * 4 + seg_);  \
            cpa16(d_ + 10240, Au4 + (size_t)grc_ * KI4 + (kb_) * 4 + seg_);  \
        }                                                                     \
        for (int i = tid; i < 256; i += 128) {                                \
            int row_ = i >> 2, seg_ = i & 3;                                  \
            int br_ = n0 + row_;                                              \
            uint32_t d_ = b_ + 20480 + row_ * 80 + seg_ * 16;                 \
            cpa16(d_,        Bg4 + (size_t)br_ * KI4 + (kb_) * 4 + seg_);    \
            cpa16(d_ + 5120, Bu4 + (size_t)br_ * KI4 + (kb_) * 4 + seg_);    \
        }                                                                     \
    } while (0)

    GU_ISSUE(0); CP_COMMIT();
    GU_ISSUE(1); CP_COMMIT();

    const int KB = HD / 64;  // 12
    for (int kb = 0; kb < KB; kb++) {
        CP_WAIT1();
        __syncthreads();
        int st = kb & 1;
        const int8_t* pAg = (const int8_t*)(dsm + st * GU_STG);
        const int8_t* pAu = pAg + 10240;
        const int8_t* pBg = pAg + 20480;
        const int8_t* pBu = pAg + 25600;
#pragma unroll
        for (int ks = 0; ks < 2; ks++) {
            int bg[4][2], bu[4][2];
#pragma unroll
            for (int nt = 0; nt < 4; nt++) {
                load_b_frag(bg[nt], pBg + (wn + nt * 8) * 80 + ks * 32, 80, lane);
                load_b_frag(bu[nt], pBu + (wn + nt * 8) * 80 + ks * 32, 80, lane);
            }
#pragma unroll
            for (int mt = 0; mt < 4; mt++) {
                int ag[4], au[4];
                load_a_frag(ag, pAg + (wm + mt * 16) * 80 + ks * 32, 80, lane);
                load_a_frag(au, pAu + (wm + mt * 16) * 80 + ks * 32, 80, lane);
#pragma unroll
                for (int nt = 0; nt < 4; nt++) {
                    mma_s8(cg[mt][nt], ag, bg[nt]);
                    mma_s8(cu[mt][nt], au, bu[nt]);
                }
            }
        }
        __syncthreads();
        if (kb + 2 < KB) GU_ISSUE(kb + 2);
        CP_COMMIT();
    }
#undef GU_ISSUE

    float wsg = g_wscale[0 * NEXP + e];
    float wsu = g_wscale[1 * NEXP + e];
    float* H = g_hidden + (size_t)e * TOK * ID;
#pragma unroll
    for (int mt = 0; mt < 4; mt++) {
        int r0 = m0 + wm + mt * 16 + (lane >> 2);
#pragma unroll
        for (int half = 0; half < 2; half++) {
            int r = r0 + half * 8;
            if (r >= n) continue;
            float sg = g_ag[e * TOK + r] * wsg;
            float su = g_au[e * TOK + r] * wsu;
            float* Hr = H + (size_t)r * ID;
#pragma unroll
            for (int nt = 0; nt < 4; nt++) {
                int c = n0 + wn + nt * 8 + (lane & 3) * 2;
#pragma unroll
                for (int cc = 0; cc < 2; cc++) {
                    int gi = cg[mt][nt][half * 2 + cc];
                    int ui = cu[mt][nt][half * 2 + cc];
                    float gg = clipf((float)gi * sg, -20.f, 20.f);
                    float uu = (float)ui * su;
                    float h = gg * fast_sigmoid(gg) * uu;
                    Hr[c + cc] = clipf(h, -1000.f, 1000.f);
                }
            }
        }
    }
}

// ---------------- GEMM 2: down, cp.async double-buffered, scatter --------
// grid (TOK/128, HD/64, NEXP), 128 threads; static smem 2 x 15360 B.
#define D_STG 15360
__global__ __launch_bounds__(128) void k_gemm_d_mma(float* __restrict__ out) {
    int e = blockIdx.z;
    int n = g_cnt[e];
    int m0 = blockIdx.x * 128;
    if (m0 >= n) return;
    int n0 = blockIdx.y * 64;

    __shared__ __align__(16) uint8_t dsm[2 * D_STG];
    uint32_t sb = smem_u32(dsm);

    const int4* A4 = (const int4*)(g_hq + (size_t)e * TOK * ID);
    const int4* B4 = (const int4*)&g_qw[2][e][0];
    const int KI4 = ID / 16;  // 128

    int tid = threadIdx.x;
    int warp = tid >> 5, lane = tid & 31;
    int wm = (warp >> 1) * 64;
    int wn = (warp & 1) * 32;

    int acc[4][4][4] = {};

#define D_ISSUE(kb_) do {                                                     \
        int st_ = (kb_) & 1; uint32_t b_ = sb + st_ * D_STG;                  \
        for (int i = tid; i < 512; i += 128) {                                \
            int row_ = i >> 2, seg_ = i & 3;                                  \
            int grc_ = min(m0 + row_, n - 1);                                 \
            cpa16(b_ + row_ * 80 + seg_ * 16,                                 \
                  A4 + (size_t)grc_ * KI4 + (kb_) * 4 + seg_);               \
        }                                                                     \
        for (int i = tid; i < 256; i += 128) {                                \
            int row_ = i >> 2, seg_ = i & 3;                                  \
            int br_ = n0 + row_;                                              \
            cpa16(b_ + 10240 + row_ * 80 + seg_ * 16,                         \
                  B4 + (size_t)br_ * KI4 + (kb_) * 4 + seg_);                \
        }                                                                     \
    } while (0)

    D_ISSUE(0); CP_COMMIT();
    D_ISSUE(1); CP_COMMIT();

    const int KB = ID / 64;  // 32
    for (int kb = 0; kb < KB; kb++) {
        CP_WAIT1();
        __syncthreads();
        int st = kb & 1;
        const int8_t* pA = (const int8_t*)(dsm + st * D_STG);
        const int8_t* pB = pA + 10240;
#pragma unroll
        for (int ks = 0; ks < 2; ks++) {
            int b[4][2];
#pragma unroll
            for (int nt = 0; nt < 4; nt++)
                load_b_frag(b[nt], pB + (wn + nt * 8) * 80 + ks * 32, 80, lane);
#pragma unroll
            for (int mt = 0; mt < 4; mt++) {
                int a[4];
                load_a_frag(a, pA + (wm + mt * 16) * 80 + ks * 32, 80, lane);
#pragma unroll
                for (int nt = 0; nt < 4; nt++)
                    mma_s8(acc[mt][nt], a, b[nt]);
            }
        }
        __syncthreads();
        if (kb + 2 < KB) D_ISSUE(kb + 2);
        CP_COMMIT();
    }
#undef D_ISSUE

    float wsd = g_wscale[2 * NEXP + e];
#pragma unroll
    for (int mt = 0; mt < 4; mt++) {
        int r0 = m0 + wm + mt * 16 + (lane >> 2);
#pragma unroll
        for (int half = 0; half < 2; half++) {
            int r = r0 + half * 8;
            if (r >= n) continue;
            float s = g_ah[e * TOK + r] * wsd;
            int t = g_lidx[e * TOK + r];
            float lw = g_lw[e * TOK + r];
            float* outr = out + (size_t)t * HD;
#pragma unroll
            for (int nt = 0; nt < 4; nt++) {
                int c = n0 + wn + nt * 8 + (lane & 3) * 2;
#pragma unroll
                for (int cc = 0; cc < 2; cc++) {
                    float y = lw * ((float)acc[mt][nt][half * 2 + cc] * s);
                    atomicAdd(outr + c + cc, y);
                }
            }
        }
    }
}

__global__ void k_clip(float* out, int n) {
    int i = blockIdx.x * blockDim.x + threadIdx.x;
    if (i < n) out[i] = clipf(out[i], -10000.f, 10000.f);
}

// ---------------- launcher ----------------
extern "C" void kernel_launch(void* const* d_in, const int* in_sizes, int n_in,
                              void* d_out, int out_size) {
    const float* x   = (const float*)d_in[0];
    const float* rw  = (const float*)d_in[1];
    const float* rb  = (const float*)d_in[2];
    const float* Wg  = (const float*)d_in[3];
    const float* Wu  = (const float*)d_in[4];
    const float* Wd  = (const float*)d_in[5];
    const float* ng  = (const float*)d_in[6];
    const float* nu  = (const float*)d_in[7];
    const float* nd  = (const float*)d_in[8];
    const float* sWg = (const float*)d_in[9];
    const float* sWu = (const float*)d_in[10];
    const float* sWd = (const float*)d_in[11];
    const float* sng = (const float*)d_in[12];
    const float* snu = (const float*)d_in[13];
    const float* snd = (const float*)d_in[14];
    float* out = (float*)d_out;

    float* logits_dst;
    if (out_size >= TOK * HD + TOK * 8) {
        logits_dst = out + (size_t)TOK * HD;
    } else {
        void* p = nullptr;
        cudaGetSymbolAddress(&p, g_logits_scratch);
        logits_dst = (float*)p;
    }

    cudaFuncSetAttribute(k_gemm_gu_mma,
                         cudaFuncAttributeMaxDynamicSharedMemorySize, GU_SMEM);

    // launch order chosen so ncu (-s 5 -c 1) profiles k_gemm_gu_mma (#6)
    k_wred_all<<<dim3(RED_BLK, NMAT), 256>>>(Wg, Wu, Wd, sWg, sWu, sWd);   // 1
    k_wfin<<<NMAT, RED_BLK>>>();                                           // 2
    k_wq_all<<<dim3(NW / 4 / 256, NMAT), 256>>>(Wg, Wu, Wd, sWg, sWu, sWd);// 3
    k_router_lists<<<TOK, 128>>>(x, rw, rb, logits_dst, out);              // 4
    k_xq_all<<<dim3(TOK / 8, NEXP), 256>>>(x, ng, nu, sng, snu);           // 5
    k_gemm_gu_mma<<<dim3(TOK / 128, ID / 64, NEXP), 128, GU_SMEM>>>();     // 6
    k_hq_all<<<dim3(TOK / 8, NEXP), 256>>>(nd, snd);                       // 7
    k_gemm_d_mma<<<dim3(TOK / 128, HD / 64, NEXP), 128>>>(out);            // 8
    k_clip<<<(TOK * HD + 255) / 256, 256>>>(out, TOK * HD);                // 9
}